// round 13
// baseline (speedup 1.0000x reference)
#include <cuda_runtime.h>
#include <cuda_bf16.h>
#include <cuda_fp16.h>

#define T_SEQ 2048
#define NB 2
#define NH 8
#define NS 32
#define DH 128
#define DMODEL 1024

__device__ float g_Q[NB*NH*T_SEQ*DH];
__device__ float g_K[NB*NH*T_SEQ*DH];
__device__ float g_V[NB*NH*T_SEQ*DH];
__device__ float g_QW[NB*NH*T_SEQ*NS];
__device__ float g_KW[NB*NH*T_SEQ*NS];
__device__ float g_O[NB*T_SEQ*DMODEL];
__device__ __half g_P[(size_t)NB*NH*T_SEQ*T_SEQ];
__device__ float g_Sinv[NB*NH*T_SEQ];

__device__ __forceinline__ float fast_exp(float x) {
    float t = x * 1.4426950408889634f;
    t = fmaxf(t, -126.0f);
    float fi = floorf(t);
    float f = t - fi;
    float p = 1.5403530e-4f;
    p = fmaf(p, f, 1.3333558e-3f);
    p = fmaf(p, f, 9.6181291e-3f);
    p = fmaf(p, f, 5.5504109e-2f);
    p = fmaf(p, f, 2.4022651e-1f);
    p = fmaf(p, f, 6.9314718e-1f);
    p = fmaf(p, f, 1.0f);
    return p * __int_as_float(((int)fi + 127) << 23);
}

__device__ __forceinline__ unsigned pack_h(float f0, float f1) {
    __half2 h2 = __floats2half2_rn(f0, f1);
    return *reinterpret_cast<unsigned*>(&h2);
}
__device__ __forceinline__ void mma_f16(float* d, const unsigned* a, unsigned b0, unsigned b1) {
    asm volatile(
        "mma.sync.aligned.m16n8k16.row.col.f32.f16.f16.f32 "
        "{%0,%1,%2,%3}, {%4,%5,%6,%7}, {%8,%9}, {%0,%1,%2,%3};"
        : "+f"(d[0]), "+f"(d[1]), "+f"(d[2]), "+f"(d[3])
        : "r"(a[0]), "r"(a[1]), "r"(a[2]), "r"(a[3]), "r"(b0), "r"(b1));
}
__device__ __forceinline__ void ldsm_x4(unsigned& r0, unsigned& r1, unsigned& r2, unsigned& r3,
                                        unsigned addr) {
    asm volatile("ldmatrix.sync.aligned.m8n8.x4.shared.b16 {%0,%1,%2,%3}, [%4];"
        : "=r"(r0), "=r"(r1), "=r"(r2), "=r"(r3) : "r"(addr));
}

__global__ void noop_kernel() {}

// Tensor GEMM v8: uniform 1-term fp16 (A packed fp16, B fp16). K-panel 32,
// double-buffered, ldmatrix. Stage (u32, stride 5120): As 0, Bs 2560.
// MODE 0: x@Wqkv+bqkv -> scatter g_Q/g_K/g_V.  MODE 1: g_O@Wout+bout -> Cout.
template<int MODE>
__global__ void __launch_bounds__(256, 2) gemm_t_kernel(
    const float* __restrict__ Ain, const float* __restrict__ Bm,
    const float* __restrict__ bias, float* __restrict__ Cout,
    int N, int K)
{
    extern __shared__ unsigned sm[];

    int t = threadIdx.x, warp = t >> 5, lane = t & 31;
    int g = lane >> 2, tig = lane & 3;
    int wm = warp >> 1, wn = warp & 1;

    int n0 = blockIdx.x * 128, m0 = blockIdx.y * 128;
    const float* A = (MODE == 1) ? (const float*)g_O : Ain;
    const float* B = Bm;
    const int lda = DMODEL, ldb = N;

    int m_a = t >> 1, ca = (t & 1) * 16;
    int n_bb = t & 127, kh = (t >> 7) * 16;

    int arow_l = (lane & 7) + ((lane >> 3) & 1) * 8;
    int akp_l  = (lane >> 4) * 4;
    int bnt_l  = (lane >> 4);
    int brow_l = lane & 7;
    int bkp_l  = ((lane >> 3) & 1) * 4;

    unsigned smem_u32 = (unsigned)__cvta_generic_to_shared((void*)sm);

    float d[2][8][4];
    #pragma unroll
    for (int mt = 0; mt < 2; mt++)
        #pragma unroll
        for (int nt = 0; nt < 8; nt++)
            #pragma unroll
            for (int q = 0; q < 4; q++) d[mt][nt][q] = 0.0f;

    float a_r[16], b_r[16];

    #define LOADP(k0) do { \
        const float* Ap = A + (size_t)(m0 + m_a) * lda + (k0) + ca; \
        _Pragma("unroll") \
        for (int j = 0; j < 4; j++) *(float4*)&a_r[j*4] = *(const float4*)(Ap + j*4); \
        const float* Bp = B + (size_t)((k0) + kh) * ldb + n0 + n_bb; \
        _Pragma("unroll") \
        for (int j = 0; j < 16; j++) b_r[j] = Bp[(size_t)j * ldb]; \
    } while (0)

    #define STOREP(st) do { \
        unsigned* base_ = sm + (st) * 5120; \
        unsigned h[8]; \
        _Pragma("unroll") \
        for (int j = 0; j < 8; j++) h[j] = pack_h(a_r[2*j], a_r[2*j+1]); \
        *(uint4*)&base_[m_a*20 + (ca>>1)]     = make_uint4(h[0],h[1],h[2],h[3]); \
        *(uint4*)&base_[m_a*20 + (ca>>1) + 4] = make_uint4(h[4],h[5],h[6],h[7]); \
        unsigned bp[8]; \
        _Pragma("unroll") \
        for (int j = 0; j < 8; j++) bp[j] = pack_h(b_r[2*j], b_r[2*j+1]); \
        *(uint4*)&base_[2560 + n_bb*20 + (kh>>1)]     = make_uint4(bp[0],bp[1],bp[2],bp[3]); \
        *(uint4*)&base_[2560 + n_bb*20 + (kh>>1) + 4] = make_uint4(bp[4],bp[5],bp[6],bp[7]); \
    } while (0)

    int nPan = K >> 5;
    LOADP(0);
    STOREP(0);
    if (nPan > 1) LOADP(32);
    __syncthreads();

    for (int p = 0; p < nPan; p++) {
        int s = p & 1;
        if (p + 1 < nPan) STOREP(s ^ 1);
        if (p + 2 < nPan) LOADP((p + 2) << 5);

        unsigned stg = smem_u32 + s * 5120 * 4;
        #pragma unroll
        for (int half = 0; half < 2; half++) {
            int base = half * 8;
            unsigned a[2][4];
            #pragma unroll
            for (int mt = 0; mt < 2; mt++) {
                unsigned addr = stg + (((wm*32 + mt*16 + arow_l)*20) + base + akp_l) * 4;
                ldsm_x4(a[mt][0], a[mt][1], a[mt][2], a[mt][3], addr);
            }
            #pragma unroll
            for (int pt = 0; pt < 4; pt++) {
                unsigned addrb = stg + 2560*4 +
                    (((wn*64 + (2*pt + bnt_l)*8 + brow_l)*20) + base + bkp_l) * 4;
                unsigned b0, b1, b2, b3;
                ldsm_x4(b0, b1, b2, b3, addrb);
                #pragma unroll
                for (int mt = 0; mt < 2; mt++) {
                    mma_f16(d[mt][2*pt],   a[mt], b0, b1);
                    mma_f16(d[mt][2*pt+1], a[mt], b2, b3);
                }
            }
        }
        __syncthreads();
    }
    #undef LOADP
    #undef STOREP

    #pragma unroll
    for (int mt = 0; mt < 2; mt++) {
        #pragma unroll
        for (int r = 0; r < 2; r++) {
            int m = m0 + wm * 32 + mt * 16 + g + r * 8;
            #pragma unroll
            for (int nt = 0; nt < 8; nt++) {
                int col = wn * 64 + nt * 8 + tig * 2;
                float v0 = d[mt][nt][r * 2 + 0] + bias[n0 + col];
                float v1 = d[mt][nt][r * 2 + 1] + bias[n0 + col + 1];
                if (MODE == 0) {
                    int grp = n0 >> 7, part = grp >> 3, h = grp & 7;
                    float* dstb = (part == 0) ? g_Q : ((part == 1) ? g_K : g_V);
                    int bb = m >> 11, tt = m & 2047;
                    float* dst = &dstb[((size_t)(bb * NH + h) * T_SEQ + tt) * DH + col];
                    dst[0] = v0; dst[1] = v1;
                } else {
                    float* dst = &Cout[(size_t)m * N + n0 + col];
                    dst[0] = v0; dst[1] = v1;
                }
            }
        }
    }
}

// splat weights v2: 32 rows per block (4 rows per warp)
__global__ void __launch_bounds__(256) weights_kernel(
    const float* __restrict__ centers, const float* __restrict__ lsc,
    const float* __restrict__ lam)
{
    __shared__ float c_sm[32][129];
    __shared__ float q_sm[32][128];

    int isK = blockIdx.y;
    int r0 = blockIdx.x * 32;
    int t = threadIdx.x, w = t >> 5, lane = t & 31;
    int h = (r0 >> 11) & 7;

    const float* cp = centers + h * NS * DH;
    for (int u = t; u < NS * DH; u += 256)
        c_sm[u >> 7][u & 127] = cp[u];

    const float* src = (isK ? g_K : g_Q) + (size_t)r0 * DH;
    for (int u = t; u < 32 * DH; u += 256)
        q_sm[u >> 7][u & 127] = src[u];
    __syncthreads();

    int s = lane;
    float scale = fast_exp(lsc[h * NS + s]);
    float inv = 1.0f / (scale + 1e-6f);
    float amp = isK ? 1.0f : fast_exp(lam[h * NS + s]);
    float coef = -0.5f * inv * inv;

    float* dstb = (isK ? g_KW : g_QW);
    #pragma unroll
    for (int rr = 0; rr < 4; rr++) {
        int row = w * 4 + rr;
        float d2 = 0.0f;
        #pragma unroll
        for (int k = 0; k < 128; k++) {
            float diff = q_sm[row][k] - c_sm[s][k];
            d2 = fmaf(diff, diff, d2);
        }
        dstb[(size_t)(r0 + row) * NS + s] = fast_exp(d2 * coef) * amp;
    }
}

// logits: 1-term fp16 (unchanged from R11)
__global__ void __launch_bounds__(256) logits_t_kernel(const float* __restrict__ temp)
{
    __shared__ unsigned Qs[64][20];
    __shared__ unsigned Ks[128][20];
    __shared__ __half  Pst[64][136];
    __shared__ float   sums_sm[2][64];

    int bh = blockIdx.y;
    int i0 = blockIdx.x * 64;
    int t = threadIdx.x, warp = t >> 5, lane = t & 31;
    int g = lane >> 2, tig = lane & 3;
    int wm = warp >> 1, wn = warp & 1;
    float invT = 1.0f / temp[0];

    {
        int row = t >> 2, s0 = (t & 3) * 8;
        const float* p = g_QW + ((size_t)bh * T_SEQ + i0 + row) * NS + s0;
        float4 f0 = *(const float4*)p, f1 = *(const float4*)(p + 4);
        float fa[8] = {f0.x,f0.y,f0.z,f0.w,f1.x,f1.y,f1.z,f1.w};
        unsigned h[4];
        #pragma unroll
        for (int j = 0; j < 4; j++) h[j] = pack_h(fa[2*j], fa[2*j+1]);
        *(uint4*)&Qs[row][s0 >> 1] = make_uint4(h[0],h[1],h[2],h[3]);
    }

    const float* KWb = g_KW + (size_t)bh * T_SEQ * NS;
    __half* Pb = g_P + ((size_t)bh * T_SEQ + i0) * T_SEQ;

    float sl0 = 0.0f, sl1 = 0.0f;

    for (int j0 = 0; j0 < T_SEQ; j0 += 128) {
        __syncthreads();
        #pragma unroll
        for (int rr = 0; rr < 2; rr++) {
            int row = (t >> 2) + rr * 64, s0 = (t & 3) * 8;
            const float* p = KWb + (size_t)(j0 + row) * NS + s0;
            float4 f0 = *(const float4*)p, f1 = *(const float4*)(p + 4);
            float fb[8] = {f0.x,f0.y,f0.z,f0.w,f1.x,f1.y,f1.z,f1.w};
            unsigned h[4];
            #pragma unroll
            for (int j = 0; j < 4; j++) h[j] = pack_h(fb[2*j], fb[2*j+1]);
            *(uint4*)&Ks[row][s0 >> 1] = make_uint4(h[0],h[1],h[2],h[3]);
        }
        __syncthreads();

        float d[8][4];
        #pragma unroll
        for (int nt = 0; nt < 8; nt++)
            #pragma unroll
            for (int q = 0; q < 4; q++) d[nt][q] = 0.0f;

        #pragma unroll
        for (int p2 = 0; p2 < 2; p2++) {
            int rm = wm * 16 + g;
            unsigned ah[4];
            ah[0] = Qs[rm][p2*8 + tig];     ah[1] = Qs[rm + 8][p2*8 + tig];
            ah[2] = Qs[rm][p2*8 + tig + 4]; ah[3] = Qs[rm + 8][p2*8 + tig + 4];

            unsigned kf[8][2];
            #pragma unroll
            for (int nt = 0; nt < 8; nt++) {
                int rn = wn * 64 + nt * 8 + g;
                kf[nt][0] = Ks[rn][p2*8 + tig]; kf[nt][1] = Ks[rn][p2*8 + tig + 4];
            }
            #pragma unroll
            for (int nt = 0; nt < 8; nt++) mma_f16(d[nt], ah, kf[nt][0], kf[nt][1]);
        }

        #pragma unroll
        for (int nt = 0; nt < 8; nt++) {
            float e0 = fast_exp(d[nt][0] * invT);
            float e1 = fast_exp(d[nt][1] * invT);
            float e2 = fast_exp(d[nt][2] * invT);
            float e3 = fast_exp(d[nt][3] * invT);
            sl0 += e0 + e1;  sl1 += e2 + e3;
            int r0 = wm * 16 + g, c = wn * 64 + nt * 8 + tig * 2;
            *(__half2*)&Pst[r0][c]     = __floats2half2_rn(e0, e1);
            *(__half2*)&Pst[r0 + 8][c] = __floats2half2_rn(e2, e3);
        }
        __syncthreads();

        #pragma unroll
        for (int r = 0; r < 8; r++) {
            int row = warp * 8 + r;
            uint2 v = *(uint2*)&Pst[row][lane * 4];
            *(uint2*)&Pb[(size_t)row * T_SEQ + j0 + lane * 4] = v;
        }
    }

    sl0 += __shfl_xor_sync(0xffffffffu, sl0, 1);
    sl0 += __shfl_xor_sync(0xffffffffu, sl0, 2);
    sl1 += __shfl_xor_sync(0xffffffffu, sl1, 1);
    sl1 += __shfl_xor_sync(0xffffffffu, sl1, 2);
    if (tig == 0) {
        sums_sm[wn][wm * 16 + g]     = sl0;
        sums_sm[wn][wm * 16 + g + 8] = sl1;
    }
    __syncthreads();
    if (t < 64)
        g_Sinv[(size_t)bh * T_SEQ + i0 + t] = 1.0f / (sums_sm[0][t] + sums_sm[1][t]);
}

// AV: P fp16 exact, V single fp16 (unchanged)
__global__ void __launch_bounds__(256, 2) av_t_kernel()
{
    extern __shared__ unsigned sm[];

    int t = threadIdx.x, warp = t >> 5, lane = t & 31;
    int g = lane >> 2, tig = lane & 3;
    int wm = warp >> 1, wn = warp & 1;

    int bh = blockIdx.y;
    int m0 = blockIdx.x * 128;
    const __half* A = g_P + (size_t)bh * T_SEQ * T_SEQ;
    const float* B = g_V + (size_t)bh * T_SEQ * DH;

    int m_a = t >> 1, ca = (t & 1) * 16;
    int n_bb = t & 127, kh = (t >> 7) * 16;

    int arow_l = (lane & 7) + ((lane >> 3) & 1) * 8;
    int akp_l  = (lane >> 4) * 4;
    int bnt_l  = (lane >> 4);
    int brow_l = lane & 7;
    int bkp_l  = ((lane >> 3) & 1) * 4;

    unsigned smem_u32 = (unsigned)__cvta_generic_to_shared((void*)sm);

    float d[2][8][4];
    #pragma unroll
    for (int mt = 0; mt < 2; mt++)
        #pragma unroll
        for (int nt = 0; nt < 8; nt++)
            #pragma unroll
            for (int q = 0; q < 4; q++) d[mt][nt][q] = 0.0f;

    uint4 pa[2]; float b_r[16];

    #define LOADP(k0) do { \
        const __half* Ap = A + (size_t)(m0 + m_a) * T_SEQ + (k0) + ca; \
        pa[0] = *(const uint4*)Ap; pa[1] = *(const uint4*)(Ap + 8); \
        const float* Bp = B + (size_t)((k0) + kh) * DH + n_bb; \
        _Pragma("unroll") \
        for (int j = 0; j < 16; j++) b_r[j] = Bp[(size_t)j * DH]; \
    } while (0)

    #define STOREP(st) do { \
        unsigned* base_ = sm + (st) * 5120; \
        *(uint4*)&base_[m_a*20 + (ca>>1)]     = pa[0]; \
        *(uint4*)&base_[m_a*20 + (ca>>1) + 4] = pa[1]; \
        unsigned bp[8]; \
        _Pragma("unroll") \
        for (int j = 0; j < 8; j++) bp[j] = pack_h(b_r[2*j], b_r[2*j+1]); \
        *(uint4*)&base_[2560 + n_bb*20 + (kh>>1)]     = make_uint4(bp[0],bp[1],bp[2],bp[3]); \
        *(uint4*)&base_[2560 + n_bb*20 + (kh>>1) + 4] = make_uint4(bp[4],bp[5],bp[6],bp[7]); \
    } while (0)

    const int nPan = T_SEQ >> 5;
    LOADP(0);
    STOREP(0);
    LOADP(32);
    __syncthreads();

    for (int p = 0; p < nPan; p++) {
        int s = p & 1;
        if (p + 1 < nPan) STOREP(s ^ 1);
        if (p + 2 < nPan) LOADP((p + 2) << 5);

        unsigned stg = smem_u32 + s * 5120 * 4;
        #pragma unroll
        for (int half = 0; half < 2; half++) {
            int base = half * 8;
            unsigned a[2][4];
            #pragma unroll
            for (int mt = 0; mt < 2; mt++) {
                unsigned addr = stg + (((wm*32 + mt*16 + arow_l)*20) + base + akp_l) * 4;
                ldsm_x4(a[mt][0], a[mt][1], a[mt][2], a[mt][3], addr);
            }
            #pragma unroll
            for (int pt = 0; pt < 4; pt++) {
                unsigned addrb = stg + 2560*4 +
                    (((wn*64 + (2*pt + bnt_l)*8 + brow_l)*20) + base + bkp_l) * 4;
                unsigned b0, b1, b2, b3;
                ldsm_x4(b0, b1, b2, b3, addrb);
                #pragma unroll
                for (int mt = 0; mt < 2; mt++) {
                    mma_f16(d[mt][2*pt],   a[mt], b0, b1);
                    mma_f16(d[mt][2*pt+1], a[mt], b2, b3);
                }
            }
        }
        __syncthreads();
    }
    #undef LOADP
    #undef STOREP

    int b = bh >> 3, h = bh & 7;
    #pragma unroll
    for (int mt = 0; mt < 2; mt++) {
        #pragma unroll
        for (int r = 0; r < 2; r++) {
            int m = m0 + wm * 32 + mt * 16 + g + r * 8;
            float inv = g_Sinv[(size_t)bh * T_SEQ + m];
            #pragma unroll
            for (int nt = 0; nt < 8; nt++) {
                int col = wn * 64 + nt * 8 + tig * 2;
                float* dst = &g_O[(size_t)(b * T_SEQ + m) * DMODEL + h * DH + col];
                dst[0] = d[mt][nt][r*2 + 0] * inv;
                dst[1] = d[mt][nt][r*2 + 1] * inv;
            }
        }
    }
}

// bhij(fp16) -> bijh(fp32) transpose + normalize (unchanged)
__global__ void __launch_bounds__(256) transpose_kernel(float* __restrict__ attn)
{
    __shared__ float p_sm[512 * 9];

    int bi = blockIdx.x;
    int b = bi >> 11, i = bi & 2047;
    int t = threadIdx.x, w = t >> 5, lane = t & 31;

    const __half* src = g_P + ((size_t)(b * NH + w) * T_SEQ + i) * T_SEQ;
    float inv = g_Sinv[(size_t)(b * NH + w) * T_SEQ + i];
    float* dst = attn + ((size_t)(b * T_SEQ + i)) * T_SEQ * NH;

    for (int c = 0; c < 4; c++) {
        #pragma unroll
        for (int r = 0; r < 8; r++) {
            int u = r * 32 + lane;
            __half2 v = *(const __half2*)&src[c * 512 + u * 2];
            float2 f = __half22float2(v);
            p_sm[(2*u)     * 9 + w] = f.x * inv;
            p_sm[(2*u + 1) * 9 + w] = f.y * inv;
        }
        __syncthreads();
        #pragma unroll
        for (int r = 0; r < 16; r++) {
            int u = r * 256 + t;
            dst[c * 4096 + u] = p_sm[(u >> 3) * 9 + (u & 7)];
        }
        __syncthreads();
    }
}

extern "C" void kernel_launch(void* const* d_in, const int* in_sizes, int n_in,
                              void* d_out, int out_size)
{
    const float* x       = (const float*)d_in[0];
    const float* Wqkv    = (const float*)d_in[1];
    const float* bqkv    = (const float*)d_in[2];
    const float* Wout    = (const float*)d_in[3];
    const float* bout    = (const float*)d_in[4];
    const float* centers = (const float*)d_in[5];
    const float* lsc     = (const float*)d_in[6];
    const float* lam     = (const float*)d_in[7];
    const float* temp    = (const float*)d_in[8];

    float* out  = (float*)d_out;
    float* attn = out + (size_t)NB * T_SEQ * DMODEL;

    const int GEMM_SMEM = 2 * 5120 * 4;   // 40960 B
    const int AV_SMEM   = 2 * 5120 * 4;   // 40960 B
    cudaFuncSetAttribute(gemm_t_kernel<0>, cudaFuncAttributeMaxDynamicSharedMemorySize, GEMM_SMEM);
    cudaFuncSetAttribute(gemm_t_kernel<1>, cudaFuncAttributeMaxDynamicSharedMemorySize, GEMM_SMEM);
    cudaFuncSetAttribute(av_t_kernel, cudaFuncAttributeMaxDynamicSharedMemorySize, AV_SMEM);

    noop_kernel<<<1, 32>>>();                                                // 1
    noop_kernel<<<1, 32>>>();                                                // 2
    noop_kernel<<<1, 32>>>();                                                // 3

    gemm_t_kernel<0><<<dim3(3 * DMODEL / 128, (NB * T_SEQ) / 128), 256, GEMM_SMEM>>>(
        x, Wqkv, bqkv, nullptr, 3 * DMODEL, DMODEL);                         // 4 <- profiled

    weights_kernel<<<dim3((NB * NH * T_SEQ) / 32, 2), 256>>>(centers, lsc, lam); // 5

    logits_t_kernel<<<dim3(T_SEQ / 64, NB * NH), 256>>>(temp);               // 6

    av_t_kernel<<<dim3(T_SEQ / 128, NB * NH), 256, AV_SMEM>>>();             // 7

    transpose_kernel<<<NB * T_SEQ, 256>>>(attn);                             // 8

    gemm_t_kernel<1><<<dim3(DMODEL / 128, (NB * T_SEQ) / 128), 256, GEMM_SMEM>>>(
        nullptr, Wout, bout, out, DMODEL, DMODEL);                           // 9
}

// round 14
// speedup vs baseline: 1.0833x; 1.0833x over previous
#include <cuda_runtime.h>
#include <cuda_bf16.h>
#include <cuda_fp16.h>

#define T_SEQ 2048
#define NB 2
#define NH 8
#define NS 32
#define DH 128
#define DMODEL 1024

__device__ float g_Q[NB*NH*T_SEQ*DH];
__device__ float g_K[NB*NH*T_SEQ*DH];
__device__ float g_V[NB*NH*T_SEQ*DH];
__device__ float g_QW[NB*NH*T_SEQ*NS];
__device__ float g_KW[NB*NH*T_SEQ*NS];
__device__ float g_O[NB*T_SEQ*DMODEL];
__device__ __half g_P[(size_t)NB*NH*T_SEQ*T_SEQ];
__device__ float g_Sinv[NB*NH*T_SEQ];

__device__ __forceinline__ float fast_exp(float x) {
    float t = x * 1.4426950408889634f;
    t = fmaxf(t, -126.0f);
    float fi = floorf(t);
    float f = t - fi;
    float p = 1.5403530e-4f;
    p = fmaf(p, f, 1.3333558e-3f);
    p = fmaf(p, f, 9.6181291e-3f);
    p = fmaf(p, f, 5.5504109e-2f);
    p = fmaf(p, f, 2.4022651e-1f);
    p = fmaf(p, f, 6.9314718e-1f);
    p = fmaf(p, f, 1.0f);
    return p * __int_as_float(((int)fi + 127) << 23);
}

__device__ __forceinline__ void split_pack_h(float f0, float f1, unsigned& hi, unsigned& lo) {
    __half2 h2 = __floats2half2_rn(f0, f1);
    hi = *reinterpret_cast<unsigned*>(&h2);
    float r0 = f0 - __low2float(h2);
    float r1 = f1 - __high2float(h2);
    __half2 l2 = __floats2half2_rn(r0, r1);
    lo = *reinterpret_cast<unsigned*>(&l2);
}
__device__ __forceinline__ unsigned pack_h(float f0, float f1) {
    __half2 h2 = __floats2half2_rn(f0, f1);
    return *reinterpret_cast<unsigned*>(&h2);
}
__device__ __forceinline__ void mma_f16(float* d, const unsigned* a, unsigned b0, unsigned b1) {
    asm volatile(
        "mma.sync.aligned.m16n8k16.row.col.f32.f16.f16.f32 "
        "{%0,%1,%2,%3}, {%4,%5,%6,%7}, {%8,%9}, {%0,%1,%2,%3};"
        : "+f"(d[0]), "+f"(d[1]), "+f"(d[2]), "+f"(d[3])
        : "r"(a[0]), "r"(a[1]), "r"(a[2]), "r"(a[3]), "r"(b0), "r"(b1));
}
__device__ __forceinline__ void ldsm_x4(unsigned& r0, unsigned& r1, unsigned& r2, unsigned& r3,
                                        unsigned addr) {
    asm volatile("ldmatrix.sync.aligned.m8n8.x4.shared.b16 {%0,%1,%2,%3}, [%4];"
        : "=r"(r0), "=r"(r1), "=r"(r2), "=r"(r3) : "r"(addr));
}

__global__ void noop_kernel() {}

// Tensor GEMM v9: A split-fp16; 2-term ONLY for the V column block of MODE 0.
// MODE 1 (Wout) and Q,K blocks use 1-term (insensitive / budgeted).
// K-panel 32, double-buffered, ldmatrix, term-outer.
// Stage (u32 units, stride 7680): As_hi 0, As_lo 2560, Bs 5120.
template<int MODE>
__global__ void __launch_bounds__(256, 2) gemm_t_kernel(
    const float* __restrict__ Ain, const float* __restrict__ Bm,
    const float* __restrict__ bias, float* __restrict__ Cout,
    int N, int K)
{
    extern __shared__ unsigned sm[];

    int t = threadIdx.x, warp = t >> 5, lane = t & 31;
    int g = lane >> 2, tig = lane & 3;
    int wm = warp >> 1, wn = warp & 1;

    int n0 = blockIdx.x * 128, m0 = blockIdx.y * 128;
    const float* A = (MODE == 1) ? (const float*)g_O : Ain;
    const float* B = Bm;
    const int lda = DMODEL, ldb = N;
    const bool twoTerm = (MODE == 0) && (n0 >= 2 * DMODEL);   // V block only

    int m_a = t >> 1, ca = (t & 1) * 16;
    int n_bb = t & 127, kh = (t >> 7) * 16;

    int arow_l = (lane & 7) + ((lane >> 3) & 1) * 8;
    int akp_l  = (lane >> 4) * 4;
    int bnt_l  = (lane >> 4);
    int brow_l = lane & 7;
    int bkp_l  = ((lane >> 3) & 1) * 4;

    unsigned smem_u32 = (unsigned)__cvta_generic_to_shared((void*)sm);

    float d[2][8][4];
    #pragma unroll
    for (int mt = 0; mt < 2; mt++)
        #pragma unroll
        for (int nt = 0; nt < 8; nt++)
            #pragma unroll
            for (int q = 0; q < 4; q++) d[mt][nt][q] = 0.0f;

    float a_r[16], b_r[16];

    #define LOADP(k0) do { \
        const float* Ap = A + (size_t)(m0 + m_a) * lda + (k0) + ca; \
        _Pragma("unroll") \
        for (int j = 0; j < 4; j++) *(float4*)&a_r[j*4] = *(const float4*)(Ap + j*4); \
        const float* Bp = B + (size_t)((k0) + kh) * ldb + n0 + n_bb; \
        _Pragma("unroll") \
        for (int j = 0; j < 16; j++) b_r[j] = Bp[(size_t)j * ldb]; \
    } while (0)

    #define STOREP(st) do { \
        unsigned* base_ = sm + (st) * 7680; \
        unsigned h0[4], l0[4], h1[4], l1[4]; \
        _Pragma("unroll") \
        for (int j = 0; j < 4; j++) split_pack_h(a_r[2*j],   a_r[2*j+1],   h0[j], l0[j]); \
        _Pragma("unroll") \
        for (int j = 0; j < 4; j++) split_pack_h(a_r[8+2*j], a_r[8+2*j+1], h1[j], l1[j]); \
        *(uint4*)&base_[m_a*20 + (ca>>1)]            = make_uint4(h0[0],h0[1],h0[2],h0[3]); \
        *(uint4*)&base_[m_a*20 + (ca>>1) + 4]        = make_uint4(h1[0],h1[1],h1[2],h1[3]); \
        if (twoTerm) { \
            *(uint4*)&base_[2560 + m_a*20 + (ca>>1)]     = make_uint4(l0[0],l0[1],l0[2],l0[3]); \
            *(uint4*)&base_[2560 + m_a*20 + (ca>>1) + 4] = make_uint4(l1[0],l1[1],l1[2],l1[3]); \
        } \
        unsigned bp[8]; \
        _Pragma("unroll") \
        for (int j = 0; j < 8; j++) bp[j] = pack_h(b_r[2*j], b_r[2*j+1]); \
        *(uint4*)&base_[5120 + n_bb*20 + (kh>>1)]     = make_uint4(bp[0],bp[1],bp[2],bp[3]); \
        *(uint4*)&base_[5120 + n_bb*20 + (kh>>1) + 4] = make_uint4(bp[4],bp[5],bp[6],bp[7]); \
    } while (0)

    int nPan = K >> 5;
    LOADP(0);
    STOREP(0);
    if (nPan > 1) LOADP(32);
    __syncthreads();

    for (int p = 0; p < nPan; p++) {
        int s = p & 1;
        if (p + 1 < nPan) STOREP(s ^ 1);
        if (p + 2 < nPan) LOADP((p + 2) << 5);

        unsigned stg = smem_u32 + s * 7680 * 4;
        #pragma unroll
        for (int half = 0; half < 2; half++) {
            int base = half * 8;
            unsigned ah[2][4], al[2][4];
            #pragma unroll
            for (int mt = 0; mt < 2; mt++) {
                unsigned addr = stg + (((wm*32 + mt*16 + arow_l)*20) + base + akp_l) * 4;
                ldsm_x4(ah[mt][0], ah[mt][1], ah[mt][2], ah[mt][3], addr);
                if (twoTerm)
                    ldsm_x4(al[mt][0], al[mt][1], al[mt][2], al[mt][3], addr + 2560*4);
            }
            #pragma unroll
            for (int pt = 0; pt < 4; pt++) {
                unsigned addrb = stg + 5120*4 +
                    (((wn*64 + (2*pt + bnt_l)*8 + brow_l)*20) + base + bkp_l) * 4;
                unsigned b0, b1, b2, b3;
                ldsm_x4(b0, b1, b2, b3, addrb);
                #pragma unroll
                for (int mt = 0; mt < 2; mt++) {
                    mma_f16(d[mt][2*pt],   ah[mt], b0, b1);
                    mma_f16(d[mt][2*pt+1], ah[mt], b2, b3);
                }
                if (twoTerm) {
                    #pragma unroll
                    for (int mt = 0; mt < 2; mt++) {
                        mma_f16(d[mt][2*pt],   al[mt], b0, b1);
                        mma_f16(d[mt][2*pt+1], al[mt], b2, b3);
                    }
                }
            }
        }
        __syncthreads();
    }
    #undef LOADP
    #undef STOREP

    #pragma unroll
    for (int mt = 0; mt < 2; mt++) {
        #pragma unroll
        for (int r = 0; r < 2; r++) {
            int m = m0 + wm * 32 + mt * 16 + g + r * 8;
            #pragma unroll
            for (int nt = 0; nt < 8; nt++) {
                int col = wn * 64 + nt * 8 + tig * 2;
                float v0 = d[mt][nt][r * 2 + 0] + bias[n0 + col];
                float v1 = d[mt][nt][r * 2 + 1] + bias[n0 + col + 1];
                if (MODE == 0) {
                    int grp = n0 >> 7, part = grp >> 3, h = grp & 7;
                    float* dstb = (part == 0) ? g_Q : ((part == 1) ? g_K : g_V);
                    int bb = m >> 11, tt = m & 2047;
                    float* dst = &dstb[((size_t)(bb * NH + h) * T_SEQ + tt) * DH + col];
                    dst[0] = v0; dst[1] = v1;
                } else {
                    float* dst = &Cout[(size_t)m * N + n0 + col];
                    dst[0] = v0; dst[1] = v1;
                }
            }
        }
    }
}

// splat weights (R11 version, 8 rows/block)
__global__ void __launch_bounds__(256) weights_kernel(
    const float* __restrict__ centers, const float* __restrict__ lsc,
    const float* __restrict__ lam)
{
    __shared__ float c_sm[32][129];
    __shared__ float q_sm[8][128];

    int isK = blockIdx.y;
    int r0 = blockIdx.x * 8;
    int t = threadIdx.x, w = t >> 5, lane = t & 31;
    int h = (r0 >> 11) & 7;

    const float* cp = centers + h * NS * DH;
    for (int u = t; u < NS * DH; u += 256)
        c_sm[u >> 7][u & 127] = cp[u];

    const float* src = (isK ? g_K : g_Q) + (size_t)r0 * DH;
    #pragma unroll
    for (int u = 0; u < 4; u++)
        q_sm[w][lane + 32*u] = src[w * DH + lane + 32*u];
    __syncthreads();

    int s = lane;
    float scale = fast_exp(lsc[h * NS + s]);
    float inv = 1.0f / (scale + 1e-6f);
    float amp = isK ? 1.0f : fast_exp(lam[h * NS + s]);
    float coef = -0.5f * inv * inv;

    float d2 = 0.0f;
    #pragma unroll
    for (int k = 0; k < 128; k++) {
        float diff = q_sm[w][k] - c_sm[s][k];
        d2 = fmaf(diff, diff, d2);
    }
    (isK ? g_KW : g_QW)[(size_t)(r0 + w) * NS + s] = fast_exp(d2 * coef) * amp;
}

// logits: 1-term fp16 (unchanged from R11)
__global__ void __launch_bounds__(256) logits_t_kernel(const float* __restrict__ temp)
{
    __shared__ unsigned Qs[64][20];
    __shared__ unsigned Ks[128][20];
    __shared__ __half  Pst[64][136];
    __shared__ float   sums_sm[2][64];

    int bh = blockIdx.y;
    int i0 = blockIdx.x * 64;
    int t = threadIdx.x, warp = t >> 5, lane = t & 31;
    int g = lane >> 2, tig = lane & 3;
    int wm = warp >> 1, wn = warp & 1;
    float invT = 1.0f / temp[0];

    {
        int row = t >> 2, s0 = (t & 3) * 8;
        const float* p = g_QW + ((size_t)bh * T_SEQ + i0 + row) * NS + s0;
        float4 f0 = *(const float4*)p, f1 = *(const float4*)(p + 4);
        float fa[8] = {f0.x,f0.y,f0.z,f0.w,f1.x,f1.y,f1.z,f1.w};
        unsigned h[4];
        #pragma unroll
        for (int j = 0; j < 4; j++) h[j] = pack_h(fa[2*j], fa[2*j+1]);
        *(uint4*)&Qs[row][s0 >> 1] = make_uint4(h[0],h[1],h[2],h[3]);
    }

    const float* KWb = g_KW + (size_t)bh * T_SEQ * NS;
    __half* Pb = g_P + ((size_t)bh * T_SEQ + i0) * T_SEQ;

    float sl0 = 0.0f, sl1 = 0.0f;

    for (int j0 = 0; j0 < T_SEQ; j0 += 128) {
        __syncthreads();
        #pragma unroll
        for (int rr = 0; rr < 2; rr++) {
            int row = (t >> 2) + rr * 64, s0 = (t & 3) * 8;
            const float* p = KWb + (size_t)(j0 + row) * NS + s0;
            float4 f0 = *(const float4*)p, f1 = *(const float4*)(p + 4);
            float fb[8] = {f0.x,f0.y,f0.z,f0.w,f1.x,f1.y,f1.z,f1.w};
            unsigned h[4];
            #pragma unroll
            for (int j = 0; j < 4; j++) h[j] = pack_h(fb[2*j], fb[2*j+1]);
            *(uint4*)&Ks[row][s0 >> 1] = make_uint4(h[0],h[1],h[2],h[3]);
        }
        __syncthreads();

        float d[8][4];
        #pragma unroll
        for (int nt = 0; nt < 8; nt++)
            #pragma unroll
            for (int q = 0; q < 4; q++) d[nt][q] = 0.0f;

        #pragma unroll
        for (int p2 = 0; p2 < 2; p2++) {
            int rm = wm * 16 + g;
            unsigned ah[4];
            ah[0] = Qs[rm][p2*8 + tig];     ah[1] = Qs[rm + 8][p2*8 + tig];
            ah[2] = Qs[rm][p2*8 + tig + 4]; ah[3] = Qs[rm + 8][p2*8 + tig + 4];

            unsigned kf[8][2];
            #pragma unroll
            for (int nt = 0; nt < 8; nt++) {
                int rn = wn * 64 + nt * 8 + g;
                kf[nt][0] = Ks[rn][p2*8 + tig]; kf[nt][1] = Ks[rn][p2*8 + tig + 4];
            }
            #pragma unroll
            for (int nt = 0; nt < 8; nt++) mma_f16(d[nt], ah, kf[nt][0], kf[nt][1]);
        }

        #pragma unroll
        for (int nt = 0; nt < 8; nt++) {
            float e0 = fast_exp(d[nt][0] * invT);
            float e1 = fast_exp(d[nt][1] * invT);
            float e2 = fast_exp(d[nt][2] * invT);
            float e3 = fast_exp(d[nt][3] * invT);
            sl0 += e0 + e1;  sl1 += e2 + e3;
            int r0 = wm * 16 + g, c = wn * 64 + nt * 8 + tig * 2;
            *(__half2*)&Pst[r0][c]     = __floats2half2_rn(e0, e1);
            *(__half2*)&Pst[r0 + 8][c] = __floats2half2_rn(e2, e3);
        }
        __syncthreads();

        #pragma unroll
        for (int r = 0; r < 8; r++) {
            int row = warp * 8 + r;
            uint2 v = *(uint2*)&Pst[row][lane * 4];
            *(uint2*)&Pb[(size_t)row * T_SEQ + j0 + lane * 4] = v;
        }
    }

    sl0 += __shfl_xor_sync(0xffffffffu, sl0, 1);
    sl0 += __shfl_xor_sync(0xffffffffu, sl0, 2);
    sl1 += __shfl_xor_sync(0xffffffffu, sl1, 1);
    sl1 += __shfl_xor_sync(0xffffffffu, sl1, 2);
    if (tig == 0) {
        sums_sm[wn][wm * 16 + g]     = sl0;
        sums_sm[wn][wm * 16 + g + 8] = sl1;
    }
    __syncthreads();
    if (t < 64)
        g_Sinv[(size_t)bh * T_SEQ + i0 + t] = 1.0f / (sums_sm[0][t] + sums_sm[1][t]);
}

// AV: P fp16 exact, V single fp16 (unchanged)
__global__ void __launch_bounds__(256, 2) av_t_kernel()
{
    extern __shared__ unsigned sm[];

    int t = threadIdx.x, warp = t >> 5, lane = t & 31;
    int g = lane >> 2, tig = lane & 3;
    int wm = warp >> 1, wn = warp & 1;

    int bh = blockIdx.y;
    int m0 = blockIdx.x * 128;
    const __half* A = g_P + (size_t)bh * T_SEQ * T_SEQ;
    const float* B = g_V + (size_t)bh * T_SEQ * DH;

    int m_a = t >> 1, ca = (t & 1) * 16;
    int n_bb = t & 127, kh = (t >> 7) * 16;

    int arow_l = (lane & 7) + ((lane >> 3) & 1) * 8;
    int akp_l  = (lane >> 4) * 4;
    int bnt_l  = (lane >> 4);
    int brow_l = lane & 7;
    int bkp_l  = ((lane >> 3) & 1) * 4;

    unsigned smem_u32 = (unsigned)__cvta_generic_to_shared((void*)sm);

    float d[2][8][4];
    #pragma unroll
    for (int mt = 0; mt < 2; mt++)
        #pragma unroll
        for (int nt = 0; nt < 8; nt++)
            #pragma unroll
            for (int q = 0; q < 4; q++) d[mt][nt][q] = 0.0f;

    uint4 pa[2]; float b_r[16];

    #define LOADP(k0) do { \
        const __half* Ap = A + (size_t)(m0 + m_a) * T_SEQ + (k0) + ca; \
        pa[0] = *(const uint4*)Ap; pa[1] = *(const uint4*)(Ap + 8); \
        const float* Bp = B + (size_t)((k0) + kh) * DH + n_bb; \
        _Pragma("unroll") \
        for (int j = 0; j < 16; j++) b_r[j] = Bp[(size_t)j * DH]; \
    } while (0)

    #define STOREP(st) do { \
        unsigned* base_ = sm + (st) * 5120; \
        *(uint4*)&base_[m_a*20 + (ca>>1)]     = pa[0]; \
        *(uint4*)&base_[m_a*20 + (ca>>1) + 4] = pa[1]; \
        unsigned bp[8]; \
        _Pragma("unroll") \
        for (int j = 0; j < 8; j++) bp[j] = pack_h(b_r[2*j], b_r[2*j+1]); \
        *(uint4*)&base_[2560 + n_bb*20 + (kh>>1)]     = make_uint4(bp[0],bp[1],bp[2],bp[3]); \
        *(uint4*)&base_[2560 + n_bb*20 + (kh>>1) + 4] = make_uint4(bp[4],bp[5],bp[6],bp[7]); \
    } while (0)

    const int nPan = T_SEQ >> 5;
    LOADP(0);
    STOREP(0);
    LOADP(32);
    __syncthreads();

    for (int p = 0; p < nPan; p++) {
        int s = p & 1;
        if (p + 1 < nPan) STOREP(s ^ 1);
        if (p + 2 < nPan) LOADP((p + 2) << 5);

        unsigned stg = smem_u32 + s * 5120 * 4;
        #pragma unroll
        for (int half = 0; half < 2; half++) {
            int base = half * 8;
            unsigned a[2][4];
            #pragma unroll
            for (int mt = 0; mt < 2; mt++) {
                unsigned addr = stg + (((wm*32 + mt*16 + arow_l)*20) + base + akp_l) * 4;
                ldsm_x4(a[mt][0], a[mt][1], a[mt][2], a[mt][3], addr);
            }
            #pragma unroll
            for (int pt = 0; pt < 4; pt++) {
                unsigned addrb = stg + 2560*4 +
                    (((wn*64 + (2*pt + bnt_l)*8 + brow_l)*20) + base + bkp_l) * 4;
                unsigned b0, b1, b2, b3;
                ldsm_x4(b0, b1, b2, b3, addrb);
                #pragma unroll
                for (int mt = 0; mt < 2; mt++) {
                    mma_f16(d[mt][2*pt],   a[mt], b0, b1);
                    mma_f16(d[mt][2*pt+1], a[mt], b2, b3);
                }
            }
        }
        __syncthreads();
    }
    #undef LOADP
    #undef STOREP

    int b = bh >> 3, h = bh & 7;
    #pragma unroll
    for (int mt = 0; mt < 2; mt++) {
        #pragma unroll
        for (int r = 0; r < 2; r++) {
            int m = m0 + wm * 32 + mt * 16 + g + r * 8;
            float inv = g_Sinv[(size_t)bh * T_SEQ + m];
            #pragma unroll
            for (int nt = 0; nt < 8; nt++) {
                int col = wn * 64 + nt * 8 + tig * 2;
                float* dst = &g_O[(size_t)(b * T_SEQ + m) * DMODEL + h * DH + col];
                dst[0] = d[mt][nt][r*2 + 0] * inv;
                dst[1] = d[mt][nt][r*2 + 1] * inv;
            }
        }
    }
}

// bhij(fp16) -> bijh(fp32) transpose + normalize (unchanged)
__global__ void __launch_bounds__(256) transpose_kernel(float* __restrict__ attn)
{
    __shared__ float p_sm[512 * 9];

    int bi = blockIdx.x;
    int b = bi >> 11, i = bi & 2047;
    int t = threadIdx.x, w = t >> 5, lane = t & 31;

    const __half* src = g_P + ((size_t)(b * NH + w) * T_SEQ + i) * T_SEQ;
    float inv = g_Sinv[(size_t)(b * NH + w) * T_SEQ + i];
    float* dst = attn + ((size_t)(b * T_SEQ + i)) * T_SEQ * NH;

    for (int c = 0; c < 4; c++) {
        #pragma unroll
        for (int r = 0; r < 8; r++) {
            int u = r * 32 + lane;
            __half2 v = *(const __half2*)&src[c * 512 + u * 2];
            float2 f = __half22float2(v);
            p_sm[(2*u)     * 9 + w] = f.x * inv;
            p_sm[(2*u + 1) * 9 + w] = f.y * inv;
        }
        __syncthreads();
        #pragma unroll
        for (int r = 0; r < 16; r++) {
            int u = r * 256 + t;
            dst[c * 4096 + u] = p_sm[(u >> 3) * 9 + (u & 7)];
        }
        __syncthreads();
    }
}

extern "C" void kernel_launch(void* const* d_in, const int* in_sizes, int n_in,
                              void* d_out, int out_size)
{
    const float* x       = (const float*)d_in[0];
    const float* Wqkv    = (const float*)d_in[1];
    const float* bqkv    = (const float*)d_in[2];
    const float* Wout    = (const float*)d_in[3];
    const float* bout    = (const float*)d_in[4];
    const float* centers = (const float*)d_in[5];
    const float* lsc     = (const float*)d_in[6];
    const float* lam     = (const float*)d_in[7];
    const float* temp    = (const float*)d_in[8];

    float* out  = (float*)d_out;
    float* attn = out + (size_t)NB * T_SEQ * DMODEL;

    const int GEMM_SMEM = 2 * 7680 * 4;   // 61440 B
    const int AV_SMEM   = 2 * 5120 * 4;   // 40960 B
    cudaFuncSetAttribute(gemm_t_kernel<0>, cudaFuncAttributeMaxDynamicSharedMemorySize, GEMM_SMEM);
    cudaFuncSetAttribute(gemm_t_kernel<1>, cudaFuncAttributeMaxDynamicSharedMemorySize, GEMM_SMEM);
    cudaFuncSetAttribute(av_t_kernel, cudaFuncAttributeMaxDynamicSharedMemorySize, AV_SMEM);

    noop_kernel<<<1, 32>>>();                                                // 1
    noop_kernel<<<1, 32>>>();                                                // 2

    gemm_t_kernel<0><<<dim3(3 * DMODEL / 128, (NB * T_SEQ) / 128), 256, GEMM_SMEM>>>(
        x, Wqkv, bqkv, nullptr, 3 * DMODEL, DMODEL);                         // 3

    weights_kernel<<<dim3((NB * NH * T_SEQ) / 8, 2), 256>>>(centers, lsc, lam); // 4 <- profiled

    logits_t_kernel<<<dim3(T_SEQ / 64, NB * NH), 256>>>(temp);               // 5

    av_t_kernel<<<dim3(T_SEQ / 128, NB * NH), 256, AV_SMEM>>>();             // 6

    transpose_kernel<<<NB * T_SEQ, 256>>>(attn);                             // 7

    gemm_t_kernel<1><<<dim3(DMODEL / 128, (NB * T_SEQ) / 128), 256, GEMM_SMEM>>>(
        nullptr, Wout, bout, out, DMODEL, DMODEL);                           // 8
}

// round 15
// speedup vs baseline: 1.1815x; 1.0906x over previous
#include <cuda_runtime.h>
#include <cuda_bf16.h>
#include <cuda_fp16.h>

#define T_SEQ 2048
#define NB 2
#define NH 8
#define NS 32
#define DH 128
#define DMODEL 1024

__device__ float g_Q[NB*NH*T_SEQ*DH];
__device__ float g_K[NB*NH*T_SEQ*DH];
__device__ float g_V[NB*NH*T_SEQ*DH];
__device__ float g_QW[NB*NH*T_SEQ*NS];
__device__ float g_KW[NB*NH*T_SEQ*NS];
__device__ float g_O[NB*T_SEQ*DMODEL];
__device__ __half g_P[(size_t)NB*NH*T_SEQ*T_SEQ];
__device__ float g_Sinv[NB*NH*T_SEQ];

__device__ __forceinline__ float fast_exp(float x) {
    float t = x * 1.4426950408889634f;
    t = fmaxf(t, -126.0f);
    float fi = floorf(t);
    float f = t - fi;
    float p = 1.5403530e-4f;
    p = fmaf(p, f, 1.3333558e-3f);
    p = fmaf(p, f, 9.6181291e-3f);
    p = fmaf(p, f, 5.5504109e-2f);
    p = fmaf(p, f, 2.4022651e-1f);
    p = fmaf(p, f, 6.9314718e-1f);
    p = fmaf(p, f, 1.0f);
    return p * __int_as_float(((int)fi + 127) << 23);
}

__device__ __forceinline__ void split_pack_h(float f0, float f1, unsigned& hi, unsigned& lo) {
    __half2 h2 = __floats2half2_rn(f0, f1);
    hi = *reinterpret_cast<unsigned*>(&h2);
    float r0 = f0 - __low2float(h2);
    float r1 = f1 - __high2float(h2);
    __half2 l2 = __floats2half2_rn(r0, r1);
    lo = *reinterpret_cast<unsigned*>(&l2);
}
__device__ __forceinline__ unsigned pack_h(float f0, float f1) {
    __half2 h2 = __floats2half2_rn(f0, f1);
    return *reinterpret_cast<unsigned*>(&h2);
}
__device__ __forceinline__ void mma_f16(float* d, const unsigned* a, unsigned b0, unsigned b1) {
    asm volatile(
        "mma.sync.aligned.m16n8k16.row.col.f32.f16.f16.f32 "
        "{%0,%1,%2,%3}, {%4,%5,%6,%7}, {%8,%9}, {%0,%1,%2,%3};"
        : "+f"(d[0]), "+f"(d[1]), "+f"(d[2]), "+f"(d[3])
        : "r"(a[0]), "r"(a[1]), "r"(a[2]), "r"(a[3]), "r"(b0), "r"(b1));
}
__device__ __forceinline__ void ldsm_x4(unsigned& r0, unsigned& r1, unsigned& r2, unsigned& r3,
                                        unsigned addr) {
    asm volatile("ldmatrix.sync.aligned.m8n8.x4.shared.b16 {%0,%1,%2,%3}, [%4];"
        : "=r"(r0), "=r"(r1), "=r"(r2), "=r"(r3) : "r"(addr));
}

__global__ void noop_kernel() {}

// Tensor GEMM v9 (unchanged from R13): A split-fp16; 2-term ONLY for V block of MODE 0.
template<int MODE>
__global__ void __launch_bounds__(256, 2) gemm_t_kernel(
    const float* __restrict__ Ain, const float* __restrict__ Bm,
    const float* __restrict__ bias, float* __restrict__ Cout,
    int N, int K)
{
    extern __shared__ unsigned sm[];

    int t = threadIdx.x, warp = t >> 5, lane = t & 31;
    int g = lane >> 2, tig = lane & 3;
    int wm = warp >> 1, wn = warp & 1;

    int n0 = blockIdx.x * 128, m0 = blockIdx.y * 128;
    const float* A = (MODE == 1) ? (const float*)g_O : Ain;
    const float* B = Bm;
    const int lda = DMODEL, ldb = N;
    const bool twoTerm = (MODE == 0) && (n0 >= 2 * DMODEL);

    int m_a = t >> 1, ca = (t & 1) * 16;
    int n_bb = t & 127, kh = (t >> 7) * 16;

    int arow_l = (lane & 7) + ((lane >> 3) & 1) * 8;
    int akp_l  = (lane >> 4) * 4;
    int bnt_l  = (lane >> 4);
    int brow_l = lane & 7;
    int bkp_l  = ((lane >> 3) & 1) * 4;

    unsigned smem_u32 = (unsigned)__cvta_generic_to_shared((void*)sm);

    float d[2][8][4];
    #pragma unroll
    for (int mt = 0; mt < 2; mt++)
        #pragma unroll
        for (int nt = 0; nt < 8; nt++)
            #pragma unroll
            for (int q = 0; q < 4; q++) d[mt][nt][q] = 0.0f;

    float a_r[16], b_r[16];

    #define LOADP(k0) do { \
        const float* Ap = A + (size_t)(m0 + m_a) * lda + (k0) + ca; \
        _Pragma("unroll") \
        for (int j = 0; j < 4; j++) *(float4*)&a_r[j*4] = *(const float4*)(Ap + j*4); \
        const float* Bp = B + (size_t)((k0) + kh) * ldb + n0 + n_bb; \
        _Pragma("unroll") \
        for (int j = 0; j < 16; j++) b_r[j] = Bp[(size_t)j * ldb]; \
    } while (0)

    #define STOREP(st) do { \
        unsigned* base_ = sm + (st) * 7680; \
        unsigned h0[4], l0[4], h1[4], l1[4]; \
        _Pragma("unroll") \
        for (int j = 0; j < 4; j++) split_pack_h(a_r[2*j],   a_r[2*j+1],   h0[j], l0[j]); \
        _Pragma("unroll") \
        for (int j = 0; j < 4; j++) split_pack_h(a_r[8+2*j], a_r[8+2*j+1], h1[j], l1[j]); \
        *(uint4*)&base_[m_a*20 + (ca>>1)]            = make_uint4(h0[0],h0[1],h0[2],h0[3]); \
        *(uint4*)&base_[m_a*20 + (ca>>1) + 4]        = make_uint4(h1[0],h1[1],h1[2],h1[3]); \
        if (twoTerm) { \
            *(uint4*)&base_[2560 + m_a*20 + (ca>>1)]     = make_uint4(l0[0],l0[1],l0[2],l0[3]); \
            *(uint4*)&base_[2560 + m_a*20 + (ca>>1) + 4] = make_uint4(l1[0],l1[1],l1[2],l1[3]); \
        } \
        unsigned bp[8]; \
        _Pragma("unroll") \
        for (int j = 0; j < 8; j++) bp[j] = pack_h(b_r[2*j], b_r[2*j+1]); \
        *(uint4*)&base_[5120 + n_bb*20 + (kh>>1)]     = make_uint4(bp[0],bp[1],bp[2],bp[3]); \
        *(uint4*)&base_[5120 + n_bb*20 + (kh>>1) + 4] = make_uint4(bp[4],bp[5],bp[6],bp[7]); \
    } while (0)

    int nPan = K >> 5;
    LOADP(0);
    STOREP(0);
    if (nPan > 1) LOADP(32);
    __syncthreads();

    for (int p = 0; p < nPan; p++) {
        int s = p & 1;
        if (p + 1 < nPan) STOREP(s ^ 1);
        if (p + 2 < nPan) LOADP((p + 2) << 5);

        unsigned stg = smem_u32 + s * 7680 * 4;
        #pragma unroll
        for (int half = 0; half < 2; half++) {
            int base = half * 8;
            unsigned ah[2][4], al[2][4];
            #pragma unroll
            for (int mt = 0; mt < 2; mt++) {
                unsigned addr = stg + (((wm*32 + mt*16 + arow_l)*20) + base + akp_l) * 4;
                ldsm_x4(ah[mt][0], ah[mt][1], ah[mt][2], ah[mt][3], addr);
                if (twoTerm)
                    ldsm_x4(al[mt][0], al[mt][1], al[mt][2], al[mt][3], addr + 2560*4);
            }
            #pragma unroll
            for (int pt = 0; pt < 4; pt++) {
                unsigned addrb = stg + 5120*4 +
                    (((wn*64 + (2*pt + bnt_l)*8 + brow_l)*20) + base + bkp_l) * 4;
                unsigned b0, b1, b2, b3;
                ldsm_x4(b0, b1, b2, b3, addrb);
                #pragma unroll
                for (int mt = 0; mt < 2; mt++) {
                    mma_f16(d[mt][2*pt],   ah[mt], b0, b1);
                    mma_f16(d[mt][2*pt+1], ah[mt], b2, b3);
                }
                if (twoTerm) {
                    #pragma unroll
                    for (int mt = 0; mt < 2; mt++) {
                        mma_f16(d[mt][2*pt],   al[mt], b0, b1);
                        mma_f16(d[mt][2*pt+1], al[mt], b2, b3);
                    }
                }
            }
        }
        __syncthreads();
    }
    #undef LOADP
    #undef STOREP

    #pragma unroll
    for (int mt = 0; mt < 2; mt++) {
        #pragma unroll
        for (int r = 0; r < 2; r++) {
            int m = m0 + wm * 32 + mt * 16 + g + r * 8;
            #pragma unroll
            for (int nt = 0; nt < 8; nt++) {
                int col = wn * 64 + nt * 8 + tig * 2;
                float v0 = d[mt][nt][r * 2 + 0] + bias[n0 + col];
                float v1 = d[mt][nt][r * 2 + 1] + bias[n0 + col + 1];
                if (MODE == 0) {
                    int grp = n0 >> 7, part = grp >> 3, h = grp & 7;
                    float* dstb = (part == 0) ? g_Q : ((part == 1) ? g_K : g_V);
                    int bb = m >> 11, tt = m & 2047;
                    float* dst = &dstb[((size_t)(bb * NH + h) * T_SEQ + tt) * DH + col];
                    dst[0] = v0; dst[1] = v1;
                } else {
                    float* dst = &Cout[(size_t)m * N + n0 + col];
                    dst[0] = v0; dst[1] = v1;
                }
            }
        }
    }
}

// weights v3 (tensor core): d2 = |q|^2 + |c|^2 - 2 q.c, dot via mma.
// Block = 128 rows of one (b,h,isK) slice; warp w -> rows w*16..+15, all 32 splats.
__global__ void __launch_bounds__(256) weights_t_kernel(
    const float* __restrict__ centers, const float* __restrict__ lsc,
    const float* __restrict__ lam)
{
    __shared__ unsigned Qs[128][68];
    __shared__ unsigned Cs[32][68];
    __shared__ float qsq_sm[128];
    __shared__ float csq_sm[32], coef_sm[32], amp_sm[32];

    int isK = blockIdx.y;
    int r0  = blockIdx.x * 128;
    int t = threadIdx.x, warp = t >> 5, lane = t & 31;
    int g = lane >> 2, tig = lane & 3;
    int h = (r0 >> 11) & 7;

    // load 128 q-rows (2 threads/row, 64 floats each), pack fp16, accumulate |q|^2
    {
        int row = t >> 1, cb = (t & 1) * 64;
        const float* p = ((isK ? g_K : g_Q) + (size_t)(r0 + row) * DH) + cb;
        float ssum = 0.0f;
        #pragma unroll
        for (int j = 0; j < 16; j++) {
            float4 f = *(const float4*)(p + j * 4);
            ssum += f.x*f.x + f.y*f.y + f.z*f.z + f.w*f.w;
            unsigned p0 = pack_h(f.x, f.y), p1 = pack_h(f.z, f.w);
            *(uint2*)&Qs[row][(cb >> 1) + j * 2] = make_uint2(p0, p1);
        }
        ssum += __shfl_xor_sync(0xffffffffu, ssum, 1);
        if ((t & 1) == 0) qsq_sm[row] = ssum;
    }
    // load 32 centers (8 threads/row, 16 floats each), pack fp16, accumulate |c|^2
    {
        int crow = t >> 3, ckb = (t & 7) * 16;
        const float* p = centers + ((size_t)(h * NS + crow)) * DH + ckb;
        float csum = 0.0f;
        #pragma unroll
        for (int j = 0; j < 4; j++) {
            float4 f = *(const float4*)(p + j * 4);
            csum += f.x*f.x + f.y*f.y + f.z*f.z + f.w*f.w;
            unsigned p0 = pack_h(f.x, f.y), p1 = pack_h(f.z, f.w);
            *(uint2*)&Cs[crow][(ckb >> 1) + j * 2] = make_uint2(p0, p1);
        }
        csum += __shfl_xor_sync(0xffffffffu, csum, 1);
        csum += __shfl_xor_sync(0xffffffffu, csum, 2);
        csum += __shfl_xor_sync(0xffffffffu, csum, 4);
        if ((t & 7) == 0) csq_sm[crow] = csum;
    }
    if (t < 32) {
        float scale = fast_exp(lsc[h * NS + t]);
        float inv = 1.0f / (scale + 1e-6f);
        coef_sm[t] = -0.5f * inv * inv;
        amp_sm[t] = isK ? 1.0f : fast_exp(lam[h * NS + t]);
    }
    __syncthreads();

    float d[4][4];
    #pragma unroll
    for (int nt = 0; nt < 4; nt++)
        #pragma unroll
        for (int q = 0; q < 4; q++) d[nt][q] = 0.0f;

    int rm = warp * 16;
    #pragma unroll
    for (int ks = 0; ks < 8; ks++) {
        unsigned a[4];
        a[0] = Qs[rm + g][ks*8 + tig];     a[1] = Qs[rm + 8 + g][ks*8 + tig];
        a[2] = Qs[rm + g][ks*8 + tig + 4]; a[3] = Qs[rm + 8 + g][ks*8 + tig + 4];
        #pragma unroll
        for (int nt = 0; nt < 4; nt++) {
            unsigned b0 = Cs[nt*8 + g][ks*8 + tig];
            unsigned b1 = Cs[nt*8 + g][ks*8 + tig + 4];
            mma_f16(d[nt], a, b0, b1);
        }
    }

    float* dst = (isK ? g_KW : g_QW) + (size_t)r0 * NS;
    #pragma unroll
    for (int nt = 0; nt < 4; nt++) {
        #pragma unroll
        for (int q = 0; q < 4; q++) {
            int rr = rm + g + ((q >= 2) ? 8 : 0);
            int s  = nt * 8 + tig * 2 + (q & 1);
            float d2 = fmaxf(qsq_sm[rr] + csq_sm[s] - 2.0f * d[nt][q], 0.0f);
            dst[(size_t)rr * NS + s] = fast_exp(d2 * coef_sm[s]) * amp_sm[s];
        }
    }
}

// logits: 1-term fp16 (unchanged)
__global__ void __launch_bounds__(256) logits_t_kernel(const float* __restrict__ temp)
{
    __shared__ unsigned Qs[64][20];
    __shared__ unsigned Ks[128][20];
    __shared__ __half  Pst[64][136];
    __shared__ float   sums_sm[2][64];

    int bh = blockIdx.y;
    int i0 = blockIdx.x * 64;
    int t = threadIdx.x, warp = t >> 5, lane = t & 31;
    int g = lane >> 2, tig = lane & 3;
    int wm = warp >> 1, wn = warp & 1;
    float invT = 1.0f / temp[0];

    {
        int row = t >> 2, s0 = (t & 3) * 8;
        const float* p = g_QW + ((size_t)bh * T_SEQ + i0 + row) * NS + s0;
        float4 f0 = *(const float4*)p, f1 = *(const float4*)(p + 4);
        float fa[8] = {f0.x,f0.y,f0.z,f0.w,f1.x,f1.y,f1.z,f1.w};
        unsigned h[4];
        #pragma unroll
        for (int j = 0; j < 4; j++) h[j] = pack_h(fa[2*j], fa[2*j+1]);
        *(uint4*)&Qs[row][s0 >> 1] = make_uint4(h[0],h[1],h[2],h[3]);
    }

    const float* KWb = g_KW + (size_t)bh * T_SEQ * NS;
    __half* Pb = g_P + ((size_t)bh * T_SEQ + i0) * T_SEQ;

    float sl0 = 0.0f, sl1 = 0.0f;

    for (int j0 = 0; j0 < T_SEQ; j0 += 128) {
        __syncthreads();
        #pragma unroll
        for (int rr = 0; rr < 2; rr++) {
            int row = (t >> 2) + rr * 64, s0 = (t & 3) * 8;
            const float* p = KWb + (size_t)(j0 + row) * NS + s0;
            float4 f0 = *(const float4*)p, f1 = *(const float4*)(p + 4);
            float fb[8] = {f0.x,f0.y,f0.z,f0.w,f1.x,f1.y,f1.z,f1.w};
            unsigned h[4];
            #pragma unroll
            for (int j = 0; j < 4; j++) h[j] = pack_h(fb[2*j], fb[2*j+1]);
            *(uint4*)&Ks[row][s0 >> 1] = make_uint4(h[0],h[1],h[2],h[3]);
        }
        __syncthreads();

        float d[8][4];
        #pragma unroll
        for (int nt = 0; nt < 8; nt++)
            #pragma unroll
            for (int q = 0; q < 4; q++) d[nt][q] = 0.0f;

        #pragma unroll
        for (int p2 = 0; p2 < 2; p2++) {
            int rm = wm * 16 + g;
            unsigned ah[4];
            ah[0] = Qs[rm][p2*8 + tig];     ah[1] = Qs[rm + 8][p2*8 + tig];
            ah[2] = Qs[rm][p2*8 + tig + 4]; ah[3] = Qs[rm + 8][p2*8 + tig + 4];

            unsigned kf[8][2];
            #pragma unroll
            for (int nt = 0; nt < 8; nt++) {
                int rn = wn * 64 + nt * 8 + g;
                kf[nt][0] = Ks[rn][p2*8 + tig]; kf[nt][1] = Ks[rn][p2*8 + tig + 4];
            }
            #pragma unroll
            for (int nt = 0; nt < 8; nt++) mma_f16(d[nt], ah, kf[nt][0], kf[nt][1]);
        }

        #pragma unroll
        for (int nt = 0; nt < 8; nt++) {
            float e0 = fast_exp(d[nt][0] * invT);
            float e1 = fast_exp(d[nt][1] * invT);
            float e2 = fast_exp(d[nt][2] * invT);
            float e3 = fast_exp(d[nt][3] * invT);
            sl0 += e0 + e1;  sl1 += e2 + e3;
            int r0 = wm * 16 + g, c = wn * 64 + nt * 8 + tig * 2;
            *(__half2*)&Pst[r0][c]     = __floats2half2_rn(e0, e1);
            *(__half2*)&Pst[r0 + 8][c] = __floats2half2_rn(e2, e3);
        }
        __syncthreads();

        #pragma unroll
        for (int r = 0; r < 8; r++) {
            int row = warp * 8 + r;
            uint2 v = *(uint2*)&Pst[row][lane * 4];
            *(uint2*)&Pb[(size_t)row * T_SEQ + j0 + lane * 4] = v;
        }
    }

    sl0 += __shfl_xor_sync(0xffffffffu, sl0, 1);
    sl0 += __shfl_xor_sync(0xffffffffu, sl0, 2);
    sl1 += __shfl_xor_sync(0xffffffffu, sl1, 1);
    sl1 += __shfl_xor_sync(0xffffffffu, sl1, 2);
    if (tig == 0) {
        sums_sm[wn][wm * 16 + g]     = sl0;
        sums_sm[wn][wm * 16 + g + 8] = sl1;
    }
    __syncthreads();
    if (t < 64)
        g_Sinv[(size_t)bh * T_SEQ + i0 + t] = 1.0f / (sums_sm[0][t] + sums_sm[1][t]);
}

// AV: P fp16 exact, V single fp16 (unchanged)
__global__ void __launch_bounds__(256, 2) av_t_kernel()
{
    extern __shared__ unsigned sm[];

    int t = threadIdx.x, warp = t >> 5, lane = t & 31;
    int g = lane >> 2, tig = lane & 3;
    int wm = warp >> 1, wn = warp & 1;

    int bh = blockIdx.y;
    int m0 = blockIdx.x * 128;
    const __half* A = g_P + (size_t)bh * T_SEQ * T_SEQ;
    const float* B = g_V + (size_t)bh * T_SEQ * DH;

    int m_a = t >> 1, ca = (t & 1) * 16;
    int n_bb = t & 127, kh = (t >> 7) * 16;

    int arow_l = (lane & 7) + ((lane >> 3) & 1) * 8;
    int akp_l  = (lane >> 4) * 4;
    int bnt_l  = (lane >> 4);
    int brow_l = lane & 7;
    int bkp_l  = ((lane >> 3) & 1) * 4;

    unsigned smem_u32 = (unsigned)__cvta_generic_to_shared((void*)sm);

    float d[2][8][4];
    #pragma unroll
    for (int mt = 0; mt < 2; mt++)
        #pragma unroll
        for (int nt = 0; nt < 8; nt++)
            #pragma unroll
            for (int q = 0; q < 4; q++) d[mt][nt][q] = 0.0f;

    uint4 pa[2]; float b_r[16];

    #define LOADP(k0) do { \
        const __half* Ap = A + (size_t)(m0 + m_a) * T_SEQ + (k0) + ca; \
        pa[0] = *(const uint4*)Ap; pa[1] = *(const uint4*)(Ap + 8); \
        const float* Bp = B + (size_t)((k0) + kh) * DH + n_bb; \
        _Pragma("unroll") \
        for (int j = 0; j < 16; j++) b_r[j] = Bp[(size_t)j * DH]; \
    } while (0)

    #define STOREP(st) do { \
        unsigned* base_ = sm + (st) * 5120; \
        *(uint4*)&base_[m_a*20 + (ca>>1)]     = pa[0]; \
        *(uint4*)&base_[m_a*20 + (ca>>1) + 4] = pa[1]; \
        unsigned bp[8]; \
        _Pragma("unroll") \
        for (int j = 0; j < 8; j++) bp[j] = pack_h(b_r[2*j], b_r[2*j+1]); \
        *(uint4*)&base_[2560 + n_bb*20 + (kh>>1)]     = make_uint4(bp[0],bp[1],bp[2],bp[3]); \
        *(uint4*)&base_[2560 + n_bb*20 + (kh>>1) + 4] = make_uint4(bp[4],bp[5],bp[6],bp[7]); \
    } while (0)

    const int nPan = T_SEQ >> 5;
    LOADP(0);
    STOREP(0);
    LOADP(32);
    __syncthreads();

    for (int p = 0; p < nPan; p++) {
        int s = p & 1;
        if (p + 1 < nPan) STOREP(s ^ 1);
        if (p + 2 < nPan) LOADP((p + 2) << 5);

        unsigned stg = smem_u32 + s * 5120 * 4;
        #pragma unroll
        for (int half = 0; half < 2; half++) {
            int base = half * 8;
            unsigned a[2][4];
            #pragma unroll
            for (int mt = 0; mt < 2; mt++) {
                unsigned addr = stg + (((wm*32 + mt*16 + arow_l)*20) + base + akp_l) * 4;
                ldsm_x4(a[mt][0], a[mt][1], a[mt][2], a[mt][3], addr);
            }
            #pragma unroll
            for (int pt = 0; pt < 4; pt++) {
                unsigned addrb = stg + 2560*4 +
                    (((wn*64 + (2*pt + bnt_l)*8 + brow_l)*20) + base + bkp_l) * 4;
                unsigned b0, b1, b2, b3;
                ldsm_x4(b0, b1, b2, b3, addrb);
                #pragma unroll
                for (int mt = 0; mt < 2; mt++) {
                    mma_f16(d[mt][2*pt],   a[mt], b0, b1);
                    mma_f16(d[mt][2*pt+1], a[mt], b2, b3);
                }
            }
        }
        __syncthreads();
    }
    #undef LOADP
    #undef STOREP

    int b = bh >> 3, h = bh & 7;
    #pragma unroll
    for (int mt = 0; mt < 2; mt++) {
        #pragma unroll
        for (int r = 0; r < 2; r++) {
            int m = m0 + wm * 32 + mt * 16 + g + r * 8;
            float inv = g_Sinv[(size_t)bh * T_SEQ + m];
            #pragma unroll
            for (int nt = 0; nt < 8; nt++) {
                int col = wn * 64 + nt * 8 + tig * 2;
                float* dst = &g_O[(size_t)(b * T_SEQ + m) * DMODEL + h * DH + col];
                dst[0] = d[mt][nt][r*2 + 0] * inv;
                dst[1] = d[mt][nt][r*2 + 1] * inv;
            }
        }
    }
}

// bhij(fp16) -> bijh(fp32) transpose + normalize (unchanged)
__global__ void __launch_bounds__(256) transpose_kernel(float* __restrict__ attn)
{
    __shared__ float p_sm[512 * 9];

    int bi = blockIdx.x;
    int b = bi >> 11, i = bi & 2047;
    int t = threadIdx.x, w = t >> 5, lane = t & 31;

    const __half* src = g_P + ((size_t)(b * NH + w) * T_SEQ + i) * T_SEQ;
    float inv = g_Sinv[(size_t)(b * NH + w) * T_SEQ + i];
    float* dst = attn + ((size_t)(b * T_SEQ + i)) * T_SEQ * NH;

    for (int c = 0; c < 4; c++) {
        #pragma unroll
        for (int r = 0; r < 8; r++) {
            int u = r * 32 + lane;
            __half2 v = *(const __half2*)&src[c * 512 + u * 2];
            float2 f = __half22float2(v);
            p_sm[(2*u)     * 9 + w] = f.x * inv;
            p_sm[(2*u + 1) * 9 + w] = f.y * inv;
        }
        __syncthreads();
        #pragma unroll
        for (int r = 0; r < 16; r++) {
            int u = r * 256 + t;
            dst[c * 4096 + u] = p_sm[(u >> 3) * 9 + (u & 7)];
        }
        __syncthreads();
    }
}

extern "C" void kernel_launch(void* const* d_in, const int* in_sizes, int n_in,
                              void* d_out, int out_size)
{
    const float* x       = (const float*)d_in[0];
    const float* Wqkv    = (const float*)d_in[1];
    const float* bqkv    = (const float*)d_in[2];
    const float* Wout    = (const float*)d_in[3];
    const float* bout    = (const float*)d_in[4];
    const float* centers = (const float*)d_in[5];
    const float* lsc     = (const float*)d_in[6];
    const float* lam     = (const float*)d_in[7];
    const float* temp    = (const float*)d_in[8];

    float* out  = (float*)d_out;
    float* attn = out + (size_t)NB * T_SEQ * DMODEL;

    const int GEMM_SMEM = 2 * 7680 * 4;   // 61440 B
    const int AV_SMEM   = 2 * 5120 * 4;   // 40960 B
    cudaFuncSetAttribute(gemm_t_kernel<0>, cudaFuncAttributeMaxDynamicSharedMemorySize, GEMM_SMEM);
    cudaFuncSetAttribute(gemm_t_kernel<1>, cudaFuncAttributeMaxDynamicSharedMemorySize, GEMM_SMEM);
    cudaFuncSetAttribute(av_t_kernel, cudaFuncAttributeMaxDynamicSharedMemorySize, AV_SMEM);

    noop_kernel<<<1, 32>>>();                                                // 1
    noop_kernel<<<1, 32>>>();                                                // 2

    gemm_t_kernel<0><<<dim3(3 * DMODEL / 128, (NB * T_SEQ) / 128), 256, GEMM_SMEM>>>(
        x, Wqkv, bqkv, nullptr, 3 * DMODEL, DMODEL);                         // 3

    weights_t_kernel<<<dim3((NB * NH * T_SEQ) / 128, 2), 256>>>(centers, lsc, lam); // 4 <- profiled

    logits_t_kernel<<<dim3(T_SEQ / 64, NB * NH), 256>>>(temp);               // 5

    av_t_kernel<<<dim3(T_SEQ / 128, NB * NH), 256, AV_SMEM>>>();             // 6

    transpose_kernel<<<NB * T_SEQ, 256>>>(attn);                             // 7

    gemm_t_kernel<1><<<dim3(DMODEL / 128, (NB * T_SEQ) / 128), 256, GEMM_SMEM>>>(
        nullptr, Wout, bout, out, DMODEL, DMODEL);                           // 8
}

// round 16
// speedup vs baseline: 1.2097x; 1.0239x over previous
#include <cuda_runtime.h>
#include <cuda_bf16.h>
#include <cuda_fp16.h>

#define T_SEQ 2048
#define NB 2
#define NH 8
#define NS 32
#define DH 128
#define DMODEL 1024

__device__ float g_Q[NB*NH*T_SEQ*DH];
__device__ float g_K[NB*NH*T_SEQ*DH];
__device__ float g_V[NB*NH*T_SEQ*DH];
__device__ float g_QW[NB*NH*T_SEQ*NS];
__device__ float g_KW[NB*NH*T_SEQ*NS];
__device__ __half g_O[NB*T_SEQ*DMODEL];                 // fp16 now
__device__ __half g_P[(size_t)NB*NH*T_SEQ*T_SEQ];
__device__ float g_Sinv[NB*NH*T_SEQ];
__device__ __half g_xh[NB*T_SEQ*DMODEL];
__device__ __half g_xl[NB*T_SEQ*DMODEL];
__device__ __half g_wqkvh[DMODEL*3*DMODEL];
__device__ __half g_wouth[DMODEL*DMODEL];

__device__ __forceinline__ float fast_exp(float x) {
    float t = x * 1.4426950408889634f;
    t = fmaxf(t, -126.0f);
    float fi = floorf(t);
    float f = t - fi;
    float p = 1.5403530e-4f;
    p = fmaf(p, f, 1.3333558e-3f);
    p = fmaf(p, f, 9.6181291e-3f);
    p = fmaf(p, f, 5.5504109e-2f);
    p = fmaf(p, f, 2.4022651e-1f);
    p = fmaf(p, f, 6.9314718e-1f);
    p = fmaf(p, f, 1.0f);
    return p * __int_as_float(((int)fi + 127) << 23);
}

__device__ __forceinline__ unsigned pack_h(float f0, float f1) {
    __half2 h2 = __floats2half2_rn(f0, f1);
    return *reinterpret_cast<unsigned*>(&h2);
}
__device__ __forceinline__ void mma_f16(float* d, const unsigned* a, unsigned b0, unsigned b1) {
    asm volatile(
        "mma.sync.aligned.m16n8k16.row.col.f32.f16.f16.f32 "
        "{%0,%1,%2,%3}, {%4,%5,%6,%7}, {%8,%9}, {%0,%1,%2,%3};"
        : "+f"(d[0]), "+f"(d[1]), "+f"(d[2]), "+f"(d[3])
        : "r"(a[0]), "r"(a[1]), "r"(a[2]), "r"(a[3]), "r"(b0), "r"(b1));
}
__device__ __forceinline__ void ldsm_x4(unsigned& r0, unsigned& r1, unsigned& r2, unsigned& r3,
                                        unsigned addr) {
    asm volatile("ldmatrix.sync.aligned.m8n8.x4.shared.b16 {%0,%1,%2,%3}, [%4];"
        : "=r"(r0), "=r"(r1), "=r"(r2), "=r"(r3) : "r"(addr));
}

// fp32 -> fp16 (hi) and optional residual (lo). 4 floats per thread.
__global__ void convert_kernel(const float* __restrict__ src, __half* __restrict__ hi,
                               __half* __restrict__ lo, int n4)
{
    int i = blockIdx.x * 256 + threadIdx.x;
    if (i >= n4) return;
    float4 f = ((const float4*)src)[i];
    __half2 h0 = __floats2half2_rn(f.x, f.y);
    __half2 h1 = __floats2half2_rn(f.z, f.w);
    ((__half2*)hi)[2*i]     = h0;
    ((__half2*)hi)[2*i + 1] = h1;
    if (lo) {
        __half2 l0 = __floats2half2_rn(f.x - __low2float(h0), f.y - __high2float(h0));
        __half2 l1 = __floats2half2_rn(f.z - __low2float(h1), f.w - __high2float(h1));
        ((__half2*)lo)[2*i]     = l0;
        ((__half2*)lo)[2*i + 1] = l1;
    }
}

// Tensor GEMM v10: fp16 inputs (pre-converted). A 2-term only for V block of MODE 0.
// K-panel 32, double-buffered, ldmatrix. Stage (u32, stride 7680): Ah 0, Al 2560, B 5120.
// MODE 0: xh(+xl)@wqkvh + bqkv -> scatter g_Q/g_K/g_V.  MODE 1: g_O@wouth + bout -> Cout.
template<int MODE>
__global__ void __launch_bounds__(256, 2) gemm_h_kernel(
    const __half* __restrict__ Ah, const __half* __restrict__ Al,
    const __half* __restrict__ Bh,
    const float* __restrict__ bias, float* __restrict__ Cout,
    int N, int K)
{
    extern __shared__ unsigned sm[];

    int t = threadIdx.x, warp = t >> 5, lane = t & 31;
    int g = lane >> 2, tig = lane & 3;
    int wm = warp >> 1, wn = warp & 1;

    int n0 = blockIdx.x * 128, m0 = blockIdx.y * 128;
    const int lda = DMODEL, ldb = N;
    const bool twoTerm = (MODE == 0) && (n0 >= 2 * DMODEL);

    int m_a = t >> 1, ca = (t & 1) * 16;      // 16 halves
    int n_bb = t & 127, kh = (t >> 7) * 16;

    int arow_l = (lane & 7) + ((lane >> 3) & 1) * 8;
    int akp_l  = (lane >> 4) * 4;
    int bnt_l  = (lane >> 4);
    int brow_l = lane & 7;
    int bkp_l  = ((lane >> 3) & 1) * 4;

    unsigned smem_u32 = (unsigned)__cvta_generic_to_shared((void*)sm);

    float d[2][8][4];
    #pragma unroll
    for (int mt = 0; mt < 2; mt++)
        #pragma unroll
        for (int nt = 0; nt < 8; nt++)
            #pragma unroll
            for (int q = 0; q < 4; q++) d[mt][nt][q] = 0.0f;

    uint4 ah0, ah1, al0, al1;
    unsigned short br[16];

    #define LOADP(k0) do { \
        const __half* Ap = Ah + (size_t)(m0 + m_a) * lda + (k0) + ca; \
        ah0 = *(const uint4*)Ap; ah1 = *(const uint4*)(Ap + 8); \
        if (twoTerm) { \
            const __half* Alp = Al + (size_t)(m0 + m_a) * lda + (k0) + ca; \
            al0 = *(const uint4*)Alp; al1 = *(const uint4*)(Alp + 8); \
        } \
        const unsigned short* Bp = (const unsigned short*)(Bh + (size_t)((k0) + kh) * ldb + n0 + n_bb); \
        _Pragma("unroll") \
        for (int j = 0; j < 16; j++) br[j] = Bp[(size_t)j * ldb]; \
    } while (0)

    #define STOREP(st) do { \
        unsigned* base_ = sm + (st) * 7680; \
        *(uint4*)&base_[m_a*20 + (ca>>1)]     = ah0; \
        *(uint4*)&base_[m_a*20 + (ca>>1) + 4] = ah1; \
        if (twoTerm) { \
            *(uint4*)&base_[2560 + m_a*20 + (ca>>1)]     = al0; \
            *(uint4*)&base_[2560 + m_a*20 + (ca>>1) + 4] = al1; \
        } \
        unsigned bp[8]; \
        _Pragma("unroll") \
        for (int j = 0; j < 8; j++) bp[j] = (unsigned)br[2*j] | ((unsigned)br[2*j+1] << 16); \
        *(uint4*)&base_[5120 + n_bb*20 + (kh>>1)]     = make_uint4(bp[0],bp[1],bp[2],bp[3]); \
        *(uint4*)&base_[5120 + n_bb*20 + (kh>>1) + 4] = make_uint4(bp[4],bp[5],bp[6],bp[7]); \
    } while (0)

    int nPan = K >> 5;
    LOADP(0);
    STOREP(0);
    if (nPan > 1) LOADP(32);
    __syncthreads();

    for (int p = 0; p < nPan; p++) {
        int s = p & 1;
        if (p + 1 < nPan) STOREP(s ^ 1);
        if (p + 2 < nPan) LOADP((p + 2) << 5);

        unsigned stg = smem_u32 + s * 7680 * 4;
        #pragma unroll
        for (int half = 0; half < 2; half++) {
            int base = half * 8;
            unsigned ah[2][4], al[2][4];
            #pragma unroll
            for (int mt = 0; mt < 2; mt++) {
                unsigned addr = stg + (((wm*32 + mt*16 + arow_l)*20) + base + akp_l) * 4;
                ldsm_x4(ah[mt][0], ah[mt][1], ah[mt][2], ah[mt][3], addr);
                if (twoTerm)
                    ldsm_x4(al[mt][0], al[mt][1], al[mt][2], al[mt][3], addr + 2560*4);
            }
            #pragma unroll
            for (int pt = 0; pt < 4; pt++) {
                unsigned addrb = stg + 5120*4 +
                    (((wn*64 + (2*pt + bnt_l)*8 + brow_l)*20) + base + bkp_l) * 4;
                unsigned b0, b1, b2, b3;
                ldsm_x4(b0, b1, b2, b3, addrb);
                #pragma unroll
                for (int mt = 0; mt < 2; mt++) {
                    mma_f16(d[mt][2*pt],   ah[mt], b0, b1);
                    mma_f16(d[mt][2*pt+1], ah[mt], b2, b3);
                }
                if (twoTerm) {
                    #pragma unroll
                    for (int mt = 0; mt < 2; mt++) {
                        mma_f16(d[mt][2*pt],   al[mt], b0, b1);
                        mma_f16(d[mt][2*pt+1], al[mt], b2, b3);
                    }
                }
            }
        }
        __syncthreads();
    }
    #undef LOADP
    #undef STOREP

    #pragma unroll
    for (int mt = 0; mt < 2; mt++) {
        #pragma unroll
        for (int r = 0; r < 2; r++) {
            int m = m0 + wm * 32 + mt * 16 + g + r * 8;
            #pragma unroll
            for (int nt = 0; nt < 8; nt++) {
                int col = wn * 64 + nt * 8 + tig * 2;
                float v0 = d[mt][nt][r * 2 + 0] + bias[n0 + col];
                float v1 = d[mt][nt][r * 2 + 1] + bias[n0 + col + 1];
                if (MODE == 0) {
                    int grp = n0 >> 7, part = grp >> 3, h = grp & 7;
                    float* dstb = (part == 0) ? g_Q : ((part == 1) ? g_K : g_V);
                    int bb = m >> 11, tt = m & 2047;
                    float* dst = &dstb[((size_t)(bb * NH + h) * T_SEQ + tt) * DH + col];
                    dst[0] = v0; dst[1] = v1;
                } else {
                    float* dst = &Cout[(size_t)m * N + n0 + col];
                    dst[0] = v0; dst[1] = v1;
                }
            }
        }
    }
}

// weights v3 (tensor core, unchanged from R14)
__global__ void __launch_bounds__(256) weights_t_kernel(
    const float* __restrict__ centers, const float* __restrict__ lsc,
    const float* __restrict__ lam)
{
    __shared__ unsigned Qs[128][68];
    __shared__ unsigned Cs[32][68];
    __shared__ float qsq_sm[128];
    __shared__ float csq_sm[32], coef_sm[32], amp_sm[32];

    int isK = blockIdx.y;
    int r0  = blockIdx.x * 128;
    int t = threadIdx.x, warp = t >> 5, lane = t & 31;
    int g = lane >> 2, tig = lane & 3;
    int h = (r0 >> 11) & 7;

    {
        int row = t >> 1, cb = (t & 1) * 64;
        const float* p = ((isK ? g_K : g_Q) + (size_t)(r0 + row) * DH) + cb;
        float ssum = 0.0f;
        #pragma unroll
        for (int j = 0; j < 16; j++) {
            float4 f = *(const float4*)(p + j * 4);
            ssum += f.x*f.x + f.y*f.y + f.z*f.z + f.w*f.w;
            unsigned p0 = pack_h(f.x, f.y), p1 = pack_h(f.z, f.w);
            *(uint2*)&Qs[row][(cb >> 1) + j * 2] = make_uint2(p0, p1);
        }
        ssum += __shfl_xor_sync(0xffffffffu, ssum, 1);
        if ((t & 1) == 0) qsq_sm[row] = ssum;
    }
    {
        int crow = t >> 3, ckb = (t & 7) * 16;
        const float* p = centers + ((size_t)(h * NS + crow)) * DH + ckb;
        float csum = 0.0f;
        #pragma unroll
        for (int j = 0; j < 4; j++) {
            float4 f = *(const float4*)(p + j * 4);
            csum += f.x*f.x + f.y*f.y + f.z*f.z + f.w*f.w;
            unsigned p0 = pack_h(f.x, f.y), p1 = pack_h(f.z, f.w);
            *(uint2*)&Cs[crow][(ckb >> 1) + j * 2] = make_uint2(p0, p1);
        }
        csum += __shfl_xor_sync(0xffffffffu, csum, 1);
        csum += __shfl_xor_sync(0xffffffffu, csum, 2);
        csum += __shfl_xor_sync(0xffffffffu, csum, 4);
        if ((t & 7) == 0) csq_sm[crow] = csum;
    }
    if (t < 32) {
        float scale = fast_exp(lsc[h * NS + t]);
        float inv = 1.0f / (scale + 1e-6f);
        coef_sm[t] = -0.5f * inv * inv;
        amp_sm[t] = isK ? 1.0f : fast_exp(lam[h * NS + t]);
    }
    __syncthreads();

    float d[4][4];
    #pragma unroll
    for (int nt = 0; nt < 4; nt++)
        #pragma unroll
        for (int q = 0; q < 4; q++) d[nt][q] = 0.0f;

    int rm = warp * 16;
    #pragma unroll
    for (int ks = 0; ks < 8; ks++) {
        unsigned a[4];
        a[0] = Qs[rm + g][ks*8 + tig];     a[1] = Qs[rm + 8 + g][ks*8 + tig];
        a[2] = Qs[rm + g][ks*8 + tig + 4]; a[3] = Qs[rm + 8 + g][ks*8 + tig + 4];
        #pragma unroll
        for (int nt = 0; nt < 4; nt++) {
            unsigned b0 = Cs[nt*8 + g][ks*8 + tig];
            unsigned b1 = Cs[nt*8 + g][ks*8 + tig + 4];
            mma_f16(d[nt], a, b0, b1);
        }
    }

    float* dst = (isK ? g_KW : g_QW) + (size_t)r0 * NS;
    #pragma unroll
    for (int nt = 0; nt < 4; nt++) {
        #pragma unroll
        for (int q = 0; q < 4; q++) {
            int rr = rm + g + ((q >= 2) ? 8 : 0);
            int s  = nt * 8 + tig * 2 + (q & 1);
            float d2 = fmaxf(qsq_sm[rr] + csq_sm[s] - 2.0f * d[nt][q], 0.0f);
            dst[(size_t)rr * NS + s] = fast_exp(d2 * coef_sm[s]) * amp_sm[s];
        }
    }
}

// logits: 1-term fp16 (unchanged)
__global__ void __launch_bounds__(256) logits_t_kernel(const float* __restrict__ temp)
{
    __shared__ unsigned Qs[64][20];
    __shared__ unsigned Ks[128][20];
    __shared__ __half  Pst[64][136];
    __shared__ float   sums_sm[2][64];

    int bh = blockIdx.y;
    int i0 = blockIdx.x * 64;
    int t = threadIdx.x, warp = t >> 5, lane = t & 31;
    int g = lane >> 2, tig = lane & 3;
    int wm = warp >> 1, wn = warp & 1;
    float invT = 1.0f / temp[0];

    {
        int row = t >> 2, s0 = (t & 3) * 8;
        const float* p = g_QW + ((size_t)bh * T_SEQ + i0 + row) * NS + s0;
        float4 f0 = *(const float4*)p, f1 = *(const float4*)(p + 4);
        float fa[8] = {f0.x,f0.y,f0.z,f0.w,f1.x,f1.y,f1.z,f1.w};
        unsigned h[4];
        #pragma unroll
        for (int j = 0; j < 4; j++) h[j] = pack_h(fa[2*j], fa[2*j+1]);
        *(uint4*)&Qs[row][s0 >> 1] = make_uint4(h[0],h[1],h[2],h[3]);
    }

    const float* KWb = g_KW + (size_t)bh * T_SEQ * NS;
    __half* Pb = g_P + ((size_t)bh * T_SEQ + i0) * T_SEQ;

    float sl0 = 0.0f, sl1 = 0.0f;

    for (int j0 = 0; j0 < T_SEQ; j0 += 128) {
        __syncthreads();
        #pragma unroll
        for (int rr = 0; rr < 2; rr++) {
            int row = (t >> 2) + rr * 64, s0 = (t & 3) * 8;
            const float* p = KWb + (size_t)(j0 + row) * NS + s0;
            float4 f0 = *(const float4*)p, f1 = *(const float4*)(p + 4);
            float fb[8] = {f0.x,f0.y,f0.z,f0.w,f1.x,f1.y,f1.z,f1.w};
            unsigned h[4];
            #pragma unroll
            for (int j = 0; j < 4; j++) h[j] = pack_h(fb[2*j], fb[2*j+1]);
            *(uint4*)&Ks[row][s0 >> 1] = make_uint4(h[0],h[1],h[2],h[3]);
        }
        __syncthreads();

        float d[8][4];
        #pragma unroll
        for (int nt = 0; nt < 8; nt++)
            #pragma unroll
            for (int q = 0; q < 4; q++) d[nt][q] = 0.0f;

        #pragma unroll
        for (int p2 = 0; p2 < 2; p2++) {
            int rm = wm * 16 + g;
            unsigned ah[4];
            ah[0] = Qs[rm][p2*8 + tig];     ah[1] = Qs[rm + 8][p2*8 + tig];
            ah[2] = Qs[rm][p2*8 + tig + 4]; ah[3] = Qs[rm + 8][p2*8 + tig + 4];

            unsigned kf[8][2];
            #pragma unroll
            for (int nt = 0; nt < 8; nt++) {
                int rn = wn * 64 + nt * 8 + g;
                kf[nt][0] = Ks[rn][p2*8 + tig]; kf[nt][1] = Ks[rn][p2*8 + tig + 4];
            }
            #pragma unroll
            for (int nt = 0; nt < 8; nt++) mma_f16(d[nt], ah, kf[nt][0], kf[nt][1]);
        }

        #pragma unroll
        for (int nt = 0; nt < 8; nt++) {
            float e0 = fast_exp(d[nt][0] * invT);
            float e1 = fast_exp(d[nt][1] * invT);
            float e2 = fast_exp(d[nt][2] * invT);
            float e3 = fast_exp(d[nt][3] * invT);
            sl0 += e0 + e1;  sl1 += e2 + e3;
            int r0 = wm * 16 + g, c = wn * 64 + nt * 8 + tig * 2;
            *(__half2*)&Pst[r0][c]     = __floats2half2_rn(e0, e1);
            *(__half2*)&Pst[r0 + 8][c] = __floats2half2_rn(e2, e3);
        }
        __syncthreads();

        #pragma unroll
        for (int r = 0; r < 8; r++) {
            int row = warp * 8 + r;
            uint2 v = *(uint2*)&Pst[row][lane * 4];
            *(uint2*)&Pb[(size_t)row * T_SEQ + j0 + lane * 4] = v;
        }
    }

    sl0 += __shfl_xor_sync(0xffffffffu, sl0, 1);
    sl0 += __shfl_xor_sync(0xffffffffu, sl0, 2);
    sl1 += __shfl_xor_sync(0xffffffffu, sl1, 1);
    sl1 += __shfl_xor_sync(0xffffffffu, sl1, 2);
    if (tig == 0) {
        sums_sm[wn][wm * 16 + g]     = sl0;
        sums_sm[wn][wm * 16 + g + 8] = sl1;
    }
    __syncthreads();
    if (t < 64)
        g_Sinv[(size_t)bh * T_SEQ + i0 + t] = 1.0f / (sums_sm[0][t] + sums_sm[1][t]);
}

// AV: P fp16, V packed fp16; epilogue writes fp16 g_O
__global__ void __launch_bounds__(256, 2) av_t_kernel()
{
    extern __shared__ unsigned sm[];

    int t = threadIdx.x, warp = t >> 5, lane = t & 31;
    int g = lane >> 2, tig = lane & 3;
    int wm = warp >> 1, wn = warp & 1;

    int bh = blockIdx.y;
    int m0 = blockIdx.x * 128;
    const __half* A = g_P + (size_t)bh * T_SEQ * T_SEQ;
    const float* B = g_V + (size_t)bh * T_SEQ * DH;

    int m_a = t >> 1, ca = (t & 1) * 16;
    int n_bb = t & 127, kh = (t >> 7) * 16;

    int arow_l = (lane & 7) + ((lane >> 3) & 1) * 8;
    int akp_l  = (lane >> 4) * 4;
    int bnt_l  = (lane >> 4);
    int brow_l = lane & 7;
    int bkp_l  = ((lane >> 3) & 1) * 4;

    unsigned smem_u32 = (unsigned)__cvta_generic_to_shared((void*)sm);

    float d[2][8][4];
    #pragma unroll
    for (int mt = 0; mt < 2; mt++)
        #pragma unroll
        for (int nt = 0; nt < 8; nt++)
            #pragma unroll
            for (int q = 0; q < 4; q++) d[mt][nt][q] = 0.0f;

    uint4 pa[2]; float b_r[16];

    #define LOADP(k0) do { \
        const __half* Ap = A + (size_t)(m0 + m_a) * T_SEQ + (k0) + ca; \
        pa[0] = *(const uint4*)Ap; pa[1] = *(const uint4*)(Ap + 8); \
        const float* Bp = B + (size_t)((k0) + kh) * DH + n_bb; \
        _Pragma("unroll") \
        for (int j = 0; j < 16; j++) b_r[j] = Bp[(size_t)j * DH]; \
    } while (0)

    #define STOREP(st) do { \
        unsigned* base_ = sm + (st) * 5120; \
        *(uint4*)&base_[m_a*20 + (ca>>1)]     = pa[0]; \
        *(uint4*)&base_[m_a*20 + (ca>>1) + 4] = pa[1]; \
        unsigned bp[8]; \
        _Pragma("unroll") \
        for (int j = 0; j < 8; j++) bp[j] = pack_h(b_r[2*j], b_r[2*j+1]); \
        *(uint4*)&base_[2560 + n_bb*20 + (kh>>1)]     = make_uint4(bp[0],bp[1],bp[2],bp[3]); \
        *(uint4*)&base_[2560 + n_bb*20 + (kh>>1) + 4] = make_uint4(bp[4],bp[5],bp[6],bp[7]); \
    } while (0)

    const int nPan = T_SEQ >> 5;
    LOADP(0);
    STOREP(0);
    LOADP(32);
    __syncthreads();

    for (int p = 0; p < nPan; p++) {
        int s = p & 1;
        if (p + 1 < nPan) STOREP(s ^ 1);
        if (p + 2 < nPan) LOADP((p + 2) << 5);

        unsigned stg = smem_u32 + s * 5120 * 4;
        #pragma unroll
        for (int half = 0; half < 2; half++) {
            int base = half * 8;
            unsigned a[2][4];
            #pragma unroll
            for (int mt = 0; mt < 2; mt++) {
                unsigned addr = stg + (((wm*32 + mt*16 + arow_l)*20) + base + akp_l) * 4;
                ldsm_x4(a[mt][0], a[mt][1], a[mt][2], a[mt][3], addr);
            }
            #pragma unroll
            for (int pt = 0; pt < 4; pt++) {
                unsigned addrb = stg + 2560*4 +
                    (((wn*64 + (2*pt + bnt_l)*8 + brow_l)*20) + base + bkp_l) * 4;
                unsigned b0, b1, b2, b3;
                ldsm_x4(b0, b1, b2, b3, addrb);
                #pragma unroll
                for (int mt = 0; mt < 2; mt++) {
                    mma_f16(d[mt][2*pt],   a[mt], b0, b1);
                    mma_f16(d[mt][2*pt+1], a[mt], b2, b3);
                }
            }
        }
        __syncthreads();
    }
    #undef LOADP
    #undef STOREP

    int b = bh >> 3, h = bh & 7;
    #pragma unroll
    for (int mt = 0; mt < 2; mt++) {
        #pragma unroll
        for (int r = 0; r < 2; r++) {
            int m = m0 + wm * 32 + mt * 16 + g + r * 8;
            float inv = g_Sinv[(size_t)bh * T_SEQ + m];
            #pragma unroll
            for (int nt = 0; nt < 8; nt++) {
                int col = wn * 64 + nt * 8 + tig * 2;
                __half2* dst = (__half2*)&g_O[(size_t)(b * T_SEQ + m) * DMODEL + h * DH + col];
                *dst = __floats2half2_rn(d[mt][nt][r*2 + 0] * inv,
                                         d[mt][nt][r*2 + 1] * inv);
            }
        }
    }
}

// bhij(fp16) -> bijh(fp32) transpose + normalize (unchanged)
__global__ void __launch_bounds__(256) transpose_kernel(float* __restrict__ attn)
{
    __shared__ float p_sm[512 * 9];

    int bi = blockIdx.x;
    int b = bi >> 11, i = bi & 2047;
    int t = threadIdx.x, w = t >> 5, lane = t & 31;

    const __half* src = g_P + ((size_t)(b * NH + w) * T_SEQ + i) * T_SEQ;
    float inv = g_Sinv[(size_t)(b * NH + w) * T_SEQ + i];
    float* dst = attn + ((size_t)(b * T_SEQ + i)) * T_SEQ * NH;

    for (int c = 0; c < 4; c++) {
        #pragma unroll
        for (int r = 0; r < 8; r++) {
            int u = r * 32 + lane;
            __half2 v = *(const __half2*)&src[c * 512 + u * 2];
            float2 f = __half22float2(v);
            p_sm[(2*u)     * 9 + w] = f.x * inv;
            p_sm[(2*u + 1) * 9 + w] = f.y * inv;
        }
        __syncthreads();
        #pragma unroll
        for (int r = 0; r < 16; r++) {
            int u = r * 256 + t;
            dst[c * 4096 + u] = p_sm[(u >> 3) * 9 + (u & 7)];
        }
        __syncthreads();
    }
}

extern "C" void kernel_launch(void* const* d_in, const int* in_sizes, int n_in,
                              void* d_out, int out_size)
{
    const float* x       = (const float*)d_in[0];
    const float* Wqkv    = (const float*)d_in[1];
    const float* bqkv    = (const float*)d_in[2];
    const float* Wout    = (const float*)d_in[3];
    const float* bout    = (const float*)d_in[4];
    const float* centers = (const float*)d_in[5];
    const float* lsc     = (const float*)d_in[6];
    const float* lam     = (const float*)d_in[7];
    const float* temp    = (const float*)d_in[8];

    float* out  = (float*)d_out;
    float* attn = out + (size_t)NB * T_SEQ * DMODEL;

    const int GEMM_SMEM = 2 * 7680 * 4;
    const int AV_SMEM   = 2 * 5120 * 4;
    cudaFuncSetAttribute(gemm_h_kernel<0>, cudaFuncAttributeMaxDynamicSharedMemorySize, GEMM_SMEM);
    cudaFuncSetAttribute(gemm_h_kernel<1>, cudaFuncAttributeMaxDynamicSharedMemorySize, GEMM_SMEM);
    cudaFuncSetAttribute(av_t_kernel, cudaFuncAttributeMaxDynamicSharedMemorySize, AV_SMEM);

    __half *d_xh, *d_xl, *d_wqkvh, *d_wouth;
    cudaGetSymbolAddress((void**)&d_xh, g_xh);
    cudaGetSymbolAddress((void**)&d_xl, g_xl);
    cudaGetSymbolAddress((void**)&d_wqkvh, g_wqkvh);
    cudaGetSymbolAddress((void**)&d_wouth, g_wouth);
    __half* d_O;
    cudaGetSymbolAddress((void**)&d_O, g_O);

    const int NX = NB * T_SEQ * DMODEL / 4;
    const int NW = DMODEL * 3 * DMODEL / 4;
    const int NO = DMODEL * DMODEL / 4;

    convert_kernel<<<(NX + 255) / 256, 256>>>(x, d_xh, d_xl, NX);            // 1
    convert_kernel<<<(NW + 255) / 256, 256>>>(Wqkv, d_wqkvh, nullptr, NW);   // 2
    convert_kernel<<<(NO + 255) / 256, 256>>>(Wout, d_wouth, nullptr, NO);   // 3

    gemm_h_kernel<0><<<dim3(3 * DMODEL / 128, (NB * T_SEQ) / 128), 256, GEMM_SMEM>>>(
        d_xh, d_xl, d_wqkvh, bqkv, nullptr, 3 * DMODEL, DMODEL);             // 4 <- profiled

    weights_t_kernel<<<dim3((NB * NH * T_SEQ) / 128, 2), 256>>>(centers, lsc, lam); // 5

    logits_t_kernel<<<dim3(T_SEQ / 64, NB * NH), 256>>>(temp);               // 6

    av_t_kernel<<<dim3(T_SEQ / 128, NB * NH), 256, AV_SMEM>>>();             // 7

    transpose_kernel<<<NB * T_SEQ, 256>>>(attn);                             // 8

    gemm_h_kernel<1><<<dim3(DMODEL / 128, (NB * T_SEQ) / 128), 256, GEMM_SMEM>>>(
        d_O, nullptr, d_wouth, bout, out, DMODEL, DMODEL);                   // 9
}

// round 17
// speedup vs baseline: 1.2375x; 1.0229x over previous
#include <cuda_runtime.h>
#include <cuda_bf16.h>
#include <cuda_fp16.h>

#define T_SEQ 2048
#define NB 2
#define NH 8
#define NS 32
#define DH 128
#define DMODEL 1024

__device__ float g_Q[NB*NH*T_SEQ*DH];
__device__ float g_K[NB*NH*T_SEQ*DH];
__device__ float g_V[NB*NH*T_SEQ*DH];
__device__ float g_QW[NB*NH*T_SEQ*NS];
__device__ float g_KW[NB*NH*T_SEQ*NS];
__device__ __half g_O[NB*T_SEQ*DMODEL];
__device__ __half g_P[(size_t)NB*NH*T_SEQ*T_SEQ];
__device__ float g_Sinv[NB*NH*T_SEQ];
__device__ __half g_xh[NB*T_SEQ*DMODEL];
__device__ __half g_xl[NB*T_SEQ*DMODEL];
__device__ __half g_wqkvh[DMODEL*3*DMODEL];
__device__ __half g_wouth[DMODEL*DMODEL];

__device__ __forceinline__ float fast_exp(float x) {
    float t = x * 1.4426950408889634f;
    t = fmaxf(t, -126.0f);
    float fi = floorf(t);
    float f = t - fi;
    float p = 1.5403530e-4f;
    p = fmaf(p, f, 1.3333558e-3f);
    p = fmaf(p, f, 9.6181291e-3f);
    p = fmaf(p, f, 5.5504109e-2f);
    p = fmaf(p, f, 2.4022651e-1f);
    p = fmaf(p, f, 6.9314718e-1f);
    p = fmaf(p, f, 1.0f);
    return p * __int_as_float(((int)fi + 127) << 23);
}

__device__ __forceinline__ unsigned pack_h(float f0, float f1) {
    __half2 h2 = __floats2half2_rn(f0, f1);
    return *reinterpret_cast<unsigned*>(&h2);
}
__device__ __forceinline__ void mma_f16(float* d, const unsigned* a, unsigned b0, unsigned b1) {
    asm volatile(
        "mma.sync.aligned.m16n8k16.row.col.f32.f16.f16.f32 "
        "{%0,%1,%2,%3}, {%4,%5,%6,%7}, {%8,%9}, {%0,%1,%2,%3};"
        : "+f"(d[0]), "+f"(d[1]), "+f"(d[2]), "+f"(d[3])
        : "r"(a[0]), "r"(a[1]), "r"(a[2]), "r"(a[3]), "r"(b0), "r"(b1));
}
__device__ __forceinline__ void ldsm_x4(unsigned& r0, unsigned& r1, unsigned& r2, unsigned& r3,
                                        unsigned addr) {
    asm volatile("ldmatrix.sync.aligned.m8n8.x4.shared.b16 {%0,%1,%2,%3}, [%4];"
        : "=r"(r0), "=r"(r1), "=r"(r2), "=r"(r3) : "r"(addr));
}

// fp32 -> fp16 (hi) and optional residual (lo)
__global__ void convert_kernel(const float* __restrict__ src, __half* __restrict__ hi,
                               __half* __restrict__ lo, int n4)
{
    int i = blockIdx.x * 256 + threadIdx.x;
    if (i >= n4) return;
    float4 f = ((const float4*)src)[i];
    __half2 h0 = __floats2half2_rn(f.x, f.y);
    __half2 h1 = __floats2half2_rn(f.z, f.w);
    ((__half2*)hi)[2*i]     = h0;
    ((__half2*)hi)[2*i + 1] = h1;
    if (lo) {
        __half2 l0 = __floats2half2_rn(f.x - __low2float(h0), f.y - __high2float(h0));
        __half2 l1 = __floats2half2_rn(f.z - __low2float(h1), f.w - __high2float(h1));
        ((__half2*)lo)[2*i]     = l0;
        ((__half2*)lo)[2*i + 1] = l1;
    }
}

// Tensor GEMM v11: fp16 inputs, uniform term count per launch (TT template).
// n0 = n_base + blockIdx.x*128 so MODE 0 can be split into QK / V launches.
// MODE 0: scatter g_Q/g_K/g_V.  MODE 1: -> Cout.
template<int MODE, int TT>
__global__ void __launch_bounds__(256, 2) gemm_h_kernel(
    const __half* __restrict__ Ah, const __half* __restrict__ Al,
    const __half* __restrict__ Bh,
    const float* __restrict__ bias, float* __restrict__ Cout,
    int N, int K, int n_base)
{
    extern __shared__ unsigned sm[];

    int t = threadIdx.x, warp = t >> 5, lane = t & 31;
    int g = lane >> 2, tig = lane & 3;
    int wm = warp >> 1, wn = warp & 1;

    int n0 = n_base + blockIdx.x * 128, m0 = blockIdx.y * 128;
    const int lda = DMODEL, ldb = N;
    const bool twoTerm = (TT != 0);

    int m_a = t >> 1, ca = (t & 1) * 16;
    int n_bb = t & 127, kh = (t >> 7) * 16;

    int arow_l = (lane & 7) + ((lane >> 3) & 1) * 8;
    int akp_l  = (lane >> 4) * 4;
    int bnt_l  = (lane >> 4);
    int brow_l = lane & 7;
    int bkp_l  = ((lane >> 3) & 1) * 4;

    unsigned smem_u32 = (unsigned)__cvta_generic_to_shared((void*)sm);

    float d[2][8][4];
    #pragma unroll
    for (int mt = 0; mt < 2; mt++)
        #pragma unroll
        for (int nt = 0; nt < 8; nt++)
            #pragma unroll
            for (int q = 0; q < 4; q++) d[mt][nt][q] = 0.0f;

    uint4 ah0, ah1, al0, al1;
    unsigned short br[16];

    #define LOADP(k0) do { \
        const __half* Ap = Ah + (size_t)(m0 + m_a) * lda + (k0) + ca; \
        ah0 = *(const uint4*)Ap; ah1 = *(const uint4*)(Ap + 8); \
        if (twoTerm) { \
            const __half* Alp = Al + (size_t)(m0 + m_a) * lda + (k0) + ca; \
            al0 = *(const uint4*)Alp; al1 = *(const uint4*)(Alp + 8); \
        } \
        const unsigned short* Bp = (const unsigned short*)(Bh + (size_t)((k0) + kh) * ldb + n0 + n_bb); \
        _Pragma("unroll") \
        for (int j = 0; j < 16; j++) br[j] = Bp[(size_t)j * ldb]; \
    } while (0)

    #define STOREP(st) do { \
        unsigned* base_ = sm + (st) * 7680; \
        *(uint4*)&base_[m_a*20 + (ca>>1)]     = ah0; \
        *(uint4*)&base_[m_a*20 + (ca>>1) + 4] = ah1; \
        if (twoTerm) { \
            *(uint4*)&base_[2560 + m_a*20 + (ca>>1)]     = al0; \
            *(uint4*)&base_[2560 + m_a*20 + (ca>>1) + 4] = al1; \
        } \
        unsigned bp[8]; \
        _Pragma("unroll") \
        for (int j = 0; j < 8; j++) bp[j] = (unsigned)br[2*j] | ((unsigned)br[2*j+1] << 16); \
        *(uint4*)&base_[5120 + n_bb*20 + (kh>>1)]     = make_uint4(bp[0],bp[1],bp[2],bp[3]); \
        *(uint4*)&base_[5120 + n_bb*20 + (kh>>1) + 4] = make_uint4(bp[4],bp[5],bp[6],bp[7]); \
    } while (0)

    int nPan = K >> 5;
    LOADP(0);
    STOREP(0);
    if (nPan > 1) LOADP(32);
    __syncthreads();

    for (int p = 0; p < nPan; p++) {
        int s = p & 1;
        if (p + 1 < nPan) STOREP(s ^ 1);
        if (p + 2 < nPan) LOADP((p + 2) << 5);

        unsigned stg = smem_u32 + s * 7680 * 4;
        #pragma unroll
        for (int half = 0; half < 2; half++) {
            int base = half * 8;
            unsigned ah[2][4], al[2][4];
            #pragma unroll
            for (int mt = 0; mt < 2; mt++) {
                unsigned addr = stg + (((wm*32 + mt*16 + arow_l)*20) + base + akp_l) * 4;
                ldsm_x4(ah[mt][0], ah[mt][1], ah[mt][2], ah[mt][3], addr);
                if (twoTerm)
                    ldsm_x4(al[mt][0], al[mt][1], al[mt][2], al[mt][3], addr + 2560*4);
            }
            #pragma unroll
            for (int pt = 0; pt < 4; pt++) {
                unsigned addrb = stg + 5120*4 +
                    (((wn*64 + (2*pt + bnt_l)*8 + brow_l)*20) + base + bkp_l) * 4;
                unsigned b0, b1, b2, b3;
                ldsm_x4(b0, b1, b2, b3, addrb);
                #pragma unroll
                for (int mt = 0; mt < 2; mt++) {
                    mma_f16(d[mt][2*pt],   ah[mt], b0, b1);
                    mma_f16(d[mt][2*pt+1], ah[mt], b2, b3);
                }
                if (twoTerm) {
                    #pragma unroll
                    for (int mt = 0; mt < 2; mt++) {
                        mma_f16(d[mt][2*pt],   al[mt], b0, b1);
                        mma_f16(d[mt][2*pt+1], al[mt], b2, b3);
                    }
                }
            }
        }
        __syncthreads();
    }
    #undef LOADP
    #undef STOREP

    #pragma unroll
    for (int mt = 0; mt < 2; mt++) {
        #pragma unroll
        for (int r = 0; r < 2; r++) {
            int m = m0 + wm * 32 + mt * 16 + g + r * 8;
            #pragma unroll
            for (int nt = 0; nt < 8; nt++) {
                int col = wn * 64 + nt * 8 + tig * 2;
                float v0 = d[mt][nt][r * 2 + 0] + bias[n0 + col];
                float v1 = d[mt][nt][r * 2 + 1] + bias[n0 + col + 1];
                if (MODE == 0) {
                    int grp = n0 >> 7, part = grp >> 3, h = grp & 7;
                    float* dstb = (part == 0) ? g_Q : ((part == 1) ? g_K : g_V);
                    int bb = m >> 11, tt = m & 2047;
                    float* dst = &dstb[((size_t)(bb * NH + h) * T_SEQ + tt) * DH + col];
                    dst[0] = v0; dst[1] = v1;
                } else {
                    float* dst = &Cout[(size_t)m * N + n0 + col];
                    dst[0] = v0; dst[1] = v1;
                }
            }
        }
    }
}

// weights v3 (tensor core, unchanged)
__global__ void __launch_bounds__(256) weights_t_kernel(
    const float* __restrict__ centers, const float* __restrict__ lsc,
    const float* __restrict__ lam)
{
    __shared__ unsigned Qs[128][68];
    __shared__ unsigned Cs[32][68];
    __shared__ float qsq_sm[128];
    __shared__ float csq_sm[32], coef_sm[32], amp_sm[32];

    int isK = blockIdx.y;
    int r0  = blockIdx.x * 128;
    int t = threadIdx.x, warp = t >> 5, lane = t & 31;
    int g = lane >> 2, tig = lane & 3;
    int h = (r0 >> 11) & 7;

    {
        int row = t >> 1, cb = (t & 1) * 64;
        const float* p = ((isK ? g_K : g_Q) + (size_t)(r0 + row) * DH) + cb;
        float ssum = 0.0f;
        #pragma unroll
        for (int j = 0; j < 16; j++) {
            float4 f = *(const float4*)(p + j * 4);
            ssum += f.x*f.x + f.y*f.y + f.z*f.z + f.w*f.w;
            unsigned p0 = pack_h(f.x, f.y), p1 = pack_h(f.z, f.w);
            *(uint2*)&Qs[row][(cb >> 1) + j * 2] = make_uint2(p0, p1);
        }
        ssum += __shfl_xor_sync(0xffffffffu, ssum, 1);
        if ((t & 1) == 0) qsq_sm[row] = ssum;
    }
    {
        int crow = t >> 3, ckb = (t & 7) * 16;
        const float* p = centers + ((size_t)(h * NS + crow)) * DH + ckb;
        float csum = 0.0f;
        #pragma unroll
        for (int j = 0; j < 4; j++) {
            float4 f = *(const float4*)(p + j * 4);
            csum += f.x*f.x + f.y*f.y + f.z*f.z + f.w*f.w;
            unsigned p0 = pack_h(f.x, f.y), p1 = pack_h(f.z, f.w);
            *(uint2*)&Cs[crow][(ckb >> 1) + j * 2] = make_uint2(p0, p1);
        }
        csum += __shfl_xor_sync(0xffffffffu, csum, 1);
        csum += __shfl_xor_sync(0xffffffffu, csum, 2);
        csum += __shfl_xor_sync(0xffffffffu, csum, 4);
        if ((t & 7) == 0) csq_sm[crow] = csum;
    }
    if (t < 32) {
        float scale = fast_exp(lsc[h * NS + t]);
        float inv = 1.0f / (scale + 1e-6f);
        coef_sm[t] = -0.5f * inv * inv;
        amp_sm[t] = isK ? 1.0f : fast_exp(lam[h * NS + t]);
    }
    __syncthreads();

    float d[4][4];
    #pragma unroll
    for (int nt = 0; nt < 4; nt++)
        #pragma unroll
        for (int q = 0; q < 4; q++) d[nt][q] = 0.0f;

    int rm = warp * 16;
    #pragma unroll
    for (int ks = 0; ks < 8; ks++) {
        unsigned a[4];
        a[0] = Qs[rm + g][ks*8 + tig];     a[1] = Qs[rm + 8 + g][ks*8 + tig];
        a[2] = Qs[rm + g][ks*8 + tig + 4]; a[3] = Qs[rm + 8 + g][ks*8 + tig + 4];
        #pragma unroll
        for (int nt = 0; nt < 4; nt++) {
            unsigned b0 = Cs[nt*8 + g][ks*8 + tig];
            unsigned b1 = Cs[nt*8 + g][ks*8 + tig + 4];
            mma_f16(d[nt], a, b0, b1);
        }
    }

    float* dst = (isK ? g_KW : g_QW) + (size_t)r0 * NS;
    #pragma unroll
    for (int nt = 0; nt < 4; nt++) {
        #pragma unroll
        for (int q = 0; q < 4; q++) {
            int rr = rm + g + ((q >= 2) ? 8 : 0);
            int s  = nt * 8 + tig * 2 + (q & 1);
            float d2 = fmaxf(qsq_sm[rr] + csq_sm[s] - 2.0f * d[nt][q], 0.0f);
            dst[(size_t)rr * NS + s] = fast_exp(d2 * coef_sm[s]) * amp_sm[s];
        }
    }
}

// logits: 1-term fp16 (unchanged)
__global__ void __launch_bounds__(256) logits_t_kernel(const float* __restrict__ temp)
{
    __shared__ unsigned Qs[64][20];
    __shared__ unsigned Ks[128][20];
    __shared__ __half  Pst[64][136];
    __shared__ float   sums_sm[2][64];

    int bh = blockIdx.y;
    int i0 = blockIdx.x * 64;
    int t = threadIdx.x, warp = t >> 5, lane = t & 31;
    int g = lane >> 2, tig = lane & 3;
    int wm = warp >> 1, wn = warp & 1;
    float invT = 1.0f / temp[0];

    {
        int row = t >> 2, s0 = (t & 3) * 8;
        const float* p = g_QW + ((size_t)bh * T_SEQ + i0 + row) * NS + s0;
        float4 f0 = *(const float4*)p, f1 = *(const float4*)(p + 4);
        float fa[8] = {f0.x,f0.y,f0.z,f0.w,f1.x,f1.y,f1.z,f1.w};
        unsigned h[4];
        #pragma unroll
        for (int j = 0; j < 4; j++) h[j] = pack_h(fa[2*j], fa[2*j+1]);
        *(uint4*)&Qs[row][s0 >> 1] = make_uint4(h[0],h[1],h[2],h[3]);
    }

    const float* KWb = g_KW + (size_t)bh * T_SEQ * NS;
    __half* Pb = g_P + ((size_t)bh * T_SEQ + i0) * T_SEQ;

    float sl0 = 0.0f, sl1 = 0.0f;

    for (int j0 = 0; j0 < T_SEQ; j0 += 128) {
        __syncthreads();
        #pragma unroll
        for (int rr = 0; rr < 2; rr++) {
            int row = (t >> 2) + rr * 64, s0 = (t & 3) * 8;
            const float* p = KWb + (size_t)(j0 + row) * NS + s0;
            float4 f0 = *(const float4*)p, f1 = *(const float4*)(p + 4);
            float fb[8] = {f0.x,f0.y,f0.z,f0.w,f1.x,f1.y,f1.z,f1.w};
            unsigned h[4];
            #pragma unroll
            for (int j = 0; j < 4; j++) h[j] = pack_h(fb[2*j], fb[2*j+1]);
            *(uint4*)&Ks[row][s0 >> 1] = make_uint4(h[0],h[1],h[2],h[3]);
        }
        __syncthreads();

        float d[8][4];
        #pragma unroll
        for (int nt = 0; nt < 8; nt++)
            #pragma unroll
            for (int q = 0; q < 4; q++) d[nt][q] = 0.0f;

        #pragma unroll
        for (int p2 = 0; p2 < 2; p2++) {
            int rm = wm * 16 + g;
            unsigned ah[4];
            ah[0] = Qs[rm][p2*8 + tig];     ah[1] = Qs[rm + 8][p2*8 + tig];
            ah[2] = Qs[rm][p2*8 + tig + 4]; ah[3] = Qs[rm + 8][p2*8 + tig + 4];

            unsigned kf[8][2];
            #pragma unroll
            for (int nt = 0; nt < 8; nt++) {
                int rn = wn * 64 + nt * 8 + g;
                kf[nt][0] = Ks[rn][p2*8 + tig]; kf[nt][1] = Ks[rn][p2*8 + tig + 4];
            }
            #pragma unroll
            for (int nt = 0; nt < 8; nt++) mma_f16(d[nt], ah, kf[nt][0], kf[nt][1]);
        }

        #pragma unroll
        for (int nt = 0; nt < 8; nt++) {
            float e0 = fast_exp(d[nt][0] * invT);
            float e1 = fast_exp(d[nt][1] * invT);
            float e2 = fast_exp(d[nt][2] * invT);
            float e3 = fast_exp(d[nt][3] * invT);
            sl0 += e0 + e1;  sl1 += e2 + e3;
            int r0 = wm * 16 + g, c = wn * 64 + nt * 8 + tig * 2;
            *(__half2*)&Pst[r0][c]     = __floats2half2_rn(e0, e1);
            *(__half2*)&Pst[r0 + 8][c] = __floats2half2_rn(e2, e3);
        }
        __syncthreads();

        #pragma unroll
        for (int r = 0; r < 8; r++) {
            int row = warp * 8 + r;
            uint2 v = *(uint2*)&Pst[row][lane * 4];
            *(uint2*)&Pb[(size_t)row * T_SEQ + j0 + lane * 4] = v;
        }
    }

    sl0 += __shfl_xor_sync(0xffffffffu, sl0, 1);
    sl0 += __shfl_xor_sync(0xffffffffu, sl0, 2);
    sl1 += __shfl_xor_sync(0xffffffffu, sl1, 1);
    sl1 += __shfl_xor_sync(0xffffffffu, sl1, 2);
    if (tig == 0) {
        sums_sm[wn][wm * 16 + g]     = sl0;
        sums_sm[wn][wm * 16 + g + 8] = sl1;
    }
    __syncthreads();
    if (t < 64)
        g_Sinv[(size_t)bh * T_SEQ + i0 + t] = 1.0f / (sums_sm[0][t] + sums_sm[1][t]);
}

// AV: P fp16, V packed fp16; fp16 g_O (unchanged)
__global__ void __launch_bounds__(256, 2) av_t_kernel()
{
    extern __shared__ unsigned sm[];

    int t = threadIdx.x, warp = t >> 5, lane = t & 31;
    int g = lane >> 2, tig = lane & 3;
    int wm = warp >> 1, wn = warp & 1;

    int bh = blockIdx.y;
    int m0 = blockIdx.x * 128;
    const __half* A = g_P + (size_t)bh * T_SEQ * T_SEQ;
    const float* B = g_V + (size_t)bh * T_SEQ * DH;

    int m_a = t >> 1, ca = (t & 1) * 16;
    int n_bb = t & 127, kh = (t >> 7) * 16;

    int arow_l = (lane & 7) + ((lane >> 3) & 1) * 8;
    int akp_l  = (lane >> 4) * 4;
    int bnt_l  = (lane >> 4);
    int brow_l = lane & 7;
    int bkp_l  = ((lane >> 3) & 1) * 4;

    unsigned smem_u32 = (unsigned)__cvta_generic_to_shared((void*)sm);

    float d[2][8][4];
    #pragma unroll
    for (int mt = 0; mt < 2; mt++)
        #pragma unroll
        for (int nt = 0; nt < 8; nt++)
            #pragma unroll
            for (int q = 0; q < 4; q++) d[mt][nt][q] = 0.0f;

    uint4 pa[2]; float b_r[16];

    #define LOADP(k0) do { \
        const __half* Ap = A + (size_t)(m0 + m_a) * T_SEQ + (k0) + ca; \
        pa[0] = *(const uint4*)Ap; pa[1] = *(const uint4*)(Ap + 8); \
        const float* Bp = B + (size_t)((k0) + kh) * DH + n_bb; \
        _Pragma("unroll") \
        for (int j = 0; j < 16; j++) b_r[j] = Bp[(size_t)j * DH]; \
    } while (0)

    #define STOREP(st) do { \
        unsigned* base_ = sm + (st) * 5120; \
        *(uint4*)&base_[m_a*20 + (ca>>1)]     = pa[0]; \
        *(uint4*)&base_[m_a*20 + (ca>>1) + 4] = pa[1]; \
        unsigned bp[8]; \
        _Pragma("unroll") \
        for (int j = 0; j < 8; j++) bp[j] = pack_h(b_r[2*j], b_r[2*j+1]); \
        *(uint4*)&base_[2560 + n_bb*20 + (kh>>1)]     = make_uint4(bp[0],bp[1],bp[2],bp[3]); \
        *(uint4*)&base_[2560 + n_bb*20 + (kh>>1) + 4] = make_uint4(bp[4],bp[5],bp[6],bp[7]); \
    } while (0)

    const int nPan = T_SEQ >> 5;
    LOADP(0);
    STOREP(0);
    LOADP(32);
    __syncthreads();

    for (int p = 0; p < nPan; p++) {
        int s = p & 1;
        if (p + 1 < nPan) STOREP(s ^ 1);
        if (p + 2 < nPan) LOADP((p + 2) << 5);

        unsigned stg = smem_u32 + s * 5120 * 4;
        #pragma unroll
        for (int half = 0; half < 2; half++) {
            int base = half * 8;
            unsigned a[2][4];
            #pragma unroll
            for (int mt = 0; mt < 2; mt++) {
                unsigned addr = stg + (((wm*32 + mt*16 + arow_l)*20) + base + akp_l) * 4;
                ldsm_x4(a[mt][0], a[mt][1], a[mt][2], a[mt][3], addr);
            }
            #pragma unroll
            for (int pt = 0; pt < 4; pt++) {
                unsigned addrb = stg + 2560*4 +
                    (((wn*64 + (2*pt + bnt_l)*8 + brow_l)*20) + base + bkp_l) * 4;
                unsigned b0, b1, b2, b3;
                ldsm_x4(b0, b1, b2, b3, addrb);
                #pragma unroll
                for (int mt = 0; mt < 2; mt++) {
                    mma_f16(d[mt][2*pt],   a[mt], b0, b1);
                    mma_f16(d[mt][2*pt+1], a[mt], b2, b3);
                }
            }
        }
        __syncthreads();
    }
    #undef LOADP
    #undef STOREP

    int b = bh >> 3, h = bh & 7;
    #pragma unroll
    for (int mt = 0; mt < 2; mt++) {
        #pragma unroll
        for (int r = 0; r < 2; r++) {
            int m = m0 + wm * 32 + mt * 16 + g + r * 8;
            float inv = g_Sinv[(size_t)bh * T_SEQ + m];
            #pragma unroll
            for (int nt = 0; nt < 8; nt++) {
                int col = wn * 64 + nt * 8 + tig * 2;
                __half2* dst = (__half2*)&g_O[(size_t)(b * T_SEQ + m) * DMODEL + h * DH + col];
                *dst = __floats2half2_rn(d[mt][nt][r*2 + 0] * inv,
                                         d[mt][nt][r*2 + 1] * inv);
            }
        }
    }
}

// bhij(fp16) -> bijh(fp32) transpose + normalize; streaming hints
__global__ void __launch_bounds__(256) transpose_kernel(float* __restrict__ attn)
{
    __shared__ float p_sm[512 * 9];

    int bi = blockIdx.x;
    int b = bi >> 11, i = bi & 2047;
    int t = threadIdx.x, w = t >> 5, lane = t & 31;

    const __half* src = g_P + ((size_t)(b * NH + w) * T_SEQ + i) * T_SEQ;
    float inv = g_Sinv[(size_t)(b * NH + w) * T_SEQ + i];
    float* dst = attn + ((size_t)(b * T_SEQ + i)) * T_SEQ * NH;

    for (int c = 0; c < 4; c++) {
        #pragma unroll
        for (int r = 0; r < 8; r++) {
            int u = r * 32 + lane;
            __half2 v = __ldcs((const __half2*)&src[c * 512 + u * 2]);
            float2 f = __half22float2(v);
            p_sm[(2*u)     * 9 + w] = f.x * inv;
            p_sm[(2*u + 1) * 9 + w] = f.y * inv;
        }
        __syncthreads();
        #pragma unroll
        for (int r = 0; r < 16; r++) {
            int u = r * 256 + t;
            __stwt(&dst[c * 4096 + u], p_sm[(u >> 3) * 9 + (u & 7)]);
        }
        __syncthreads();
    }
}

extern "C" void kernel_launch(void* const* d_in, const int* in_sizes, int n_in,
                              void* d_out, int out_size)
{
    const float* x       = (const float*)d_in[0];
    const float* Wqkv    = (const float*)d_in[1];
    const float* bqkv    = (const float*)d_in[2];
    const float* Wout    = (const float*)d_in[3];
    const float* bout    = (const float*)d_in[4];
    const float* centers = (const float*)d_in[5];
    const float* lsc     = (const float*)d_in[6];
    const float* lam     = (const float*)d_in[7];
    const float* temp    = (const float*)d_in[8];

    float* out  = (float*)d_out;
    float* attn = out + (size_t)NB * T_SEQ * DMODEL;

    const int GEMM_SMEM = 2 * 7680 * 4;
    const int AV_SMEM   = 2 * 5120 * 4;
    cudaFuncSetAttribute((const void*)gemm_h_kernel<0,0>, cudaFuncAttributeMaxDynamicSharedMemorySize, GEMM_SMEM);
    cudaFuncSetAttribute((const void*)gemm_h_kernel<0,1>, cudaFuncAttributeMaxDynamicSharedMemorySize, GEMM_SMEM);
    cudaFuncSetAttribute((const void*)gemm_h_kernel<1,0>, cudaFuncAttributeMaxDynamicSharedMemorySize, GEMM_SMEM);
    cudaFuncSetAttribute((const void*)av_t_kernel, cudaFuncAttributeMaxDynamicSharedMemorySize, AV_SMEM);

    __half *d_xh, *d_xl, *d_wqkvh, *d_wouth, *d_O;
    cudaGetSymbolAddress((void**)&d_xh, g_xh);
    cudaGetSymbolAddress((void**)&d_xl, g_xl);
    cudaGetSymbolAddress((void**)&d_wqkvh, g_wqkvh);
    cudaGetSymbolAddress((void**)&d_wouth, g_wouth);
    cudaGetSymbolAddress((void**)&d_O, g_O);

    const int NX = NB * T_SEQ * DMODEL / 4;
    const int NW = DMODEL * 3 * DMODEL / 4;
    const int NO = DMODEL * DMODEL / 4;

    convert_kernel<<<(NX + 255) / 256, 256>>>(x, d_xh, d_xl, NX);            // 1
    convert_kernel<<<(NW + 255) / 256, 256>>>(Wqkv, d_wqkvh, nullptr, NW);   // 2
    convert_kernel<<<(NO + 255) / 256, 256>>>(Wout, d_wouth, nullptr, NO);   // 3

    // V part (2-term), profiled
    gemm_h_kernel<0,1><<<dim3(DMODEL / 128, (NB * T_SEQ) / 128), 256, GEMM_SMEM>>>(
        d_xh, d_xl, d_wqkvh, bqkv, nullptr, 3 * DMODEL, DMODEL, 2 * DMODEL); // 4 <- profiled

    // QK part (1-term)
    gemm_h_kernel<0,0><<<dim3(2 * DMODEL / 128, (NB * T_SEQ) / 128), 256, GEMM_SMEM>>>(
        d_xh, nullptr, d_wqkvh, bqkv, nullptr, 3 * DMODEL, DMODEL, 0);       // 5

    weights_t_kernel<<<dim3((NB * NH * T_SEQ) / 128, 2), 256>>>(centers, lsc, lam); // 6

    logits_t_kernel<<<dim3(T_SEQ / 64, NB * NH), 256>>>(temp);               // 7

    av_t_kernel<<<dim3(T_SEQ / 128, NB * NH), 256, AV_SMEM>>>();             // 8

    transpose_kernel<<<NB * T_SEQ, 256>>>(attn);                             // 9

    gemm_h_kernel<1,0><<<dim3(DMODEL / 128, (NB * T_SEQ) / 128), 256, GEMM_SMEM>>>(
        d_O, nullptr, d_wouth, bout, out, DMODEL, DMODEL, 0);                // 10
}